// round 6
// baseline (speedup 1.0000x reference)
#include <cuda_runtime.h>
#include <cuda_fp16.h>
#include <math.h>
#include <stdint.h>

#define Bdim 8
#define Sdim 4096
#define Ddim 512
#define Mrows (Bdim * Sdim)
#define NC 32
#define CL (Sdim / NC)

// ---------------- scratch ----------------
__device__ __half g_omega[(size_t)Mrows * Ddim];
__device__ __half g_mag  [(size_t)Mrows * Ddim];
__device__ __half g_gate [(size_t)Mrows * Ddim];
__device__ __half g_qoff [(size_t)Mrows * Ddim];
__device__ __half g_phii [(size_t)Mrows * Ddim];
__device__ __half g_xf  [(size_t)Mrows * Ddim];
__device__ __half g_p1f [(size_t)Mrows * Ddim];
__device__ __half g_ctxf[(size_t)Mrows * 4 * Ddim];
__device__ __half g_hf  [(size_t)Mrows * 2 * Ddim];
__device__ float4 g_csum[Bdim * NC * Ddim];
__device__ float4 g_coff[Bdim * NC * Ddim];
__device__ __half g_wf[4194304];

#define OFF_OM   0
#define OFF_MAG  262144
#define OFF_GATE 524288
#define OFF_QOFF 786432
#define OFF_P1   1048576
#define OFF_P2   1310720
#define OFF_O1   1572864
#define OFF_O2   3670016

// ---------------- helpers ----------------
__device__ __forceinline__ uint32_t smem_u32(const void* p) {
    uint32_t a;
    asm("{ .reg .u64 t; cvta.to.shared.u64 t, %1; cvt.u32.u64 %0, t; }" : "=r"(a) : "l"(p));
    return a;
}
#define CP16(so, gp) \
    asm volatile("cp.async.cg.shared.global [%0], [%1], 16;" :: "r"(so), "l"(gp) : "memory")
#define CP_COMMIT() asm volatile("cp.async.commit_group;" ::: "memory")
#define CP_WAIT1()  asm volatile("cp.async.wait_group 1;" ::: "memory")
#define CP_WAIT0()  asm volatile("cp.async.wait_group 0;" ::: "memory")

#define LDSM4(r0, r1, r2, r3, a)                                              \
    asm volatile("ldmatrix.sync.aligned.m8n8.x4.shared.b16 {%0,%1,%2,%3}, [%4];" \
                 : "=r"(r0), "=r"(r1), "=r"(r2), "=r"(r3) : "r"(a))

__device__ __forceinline__ void mma16816(float* c, const uint32_t* a, const uint32_t* b) {
    asm volatile(
        "mma.sync.aligned.m16n8k16.row.col.f32.f16.f16.f32 "
        "{%0,%1,%2,%3}, {%4,%5,%6,%7}, {%8,%9}, {%0,%1,%2,%3};"
        : "+f"(c[0]), "+f"(c[1]), "+f"(c[2]), "+f"(c[3])
        : "r"(a[0]), "r"(a[1]), "r"(a[2]), "r"(a[3]), "r"(b[0]), "r"(b[1]));
}

__device__ __forceinline__ float act_apply(float v, int ACT) {
    if (ACT == 1) return 1.0f / (1.0f + expf(-v));
    if (ACT == 2) return 5.0f / (1.0f + expf(-v));
    if (ACT == 3) return 0.5f * v * (1.0f + erff(v * 0.70710678118654752f));
    return v;
}

// W[K,N] fp32 -> T[N,K] fp16 (transpose + convert)
__global__ void wconv_kernel(const float* __restrict__ W, __half* __restrict__ T,
                             int K, int N)
{
    __shared__ float t[32][33];
    const int tx = threadIdx.x, ty = threadIdx.y;
    const int n0 = blockIdx.x * 32, k0 = blockIdx.y * 32;
    #pragma unroll
    for (int i = 0; i < 32; i += 8)
        t[ty + i][tx] = W[(size_t)(k0 + ty + i) * N + n0 + tx];
    __syncthreads();
    #pragma unroll
    for (int i = 0; i < 32; i += 8)
        T[(size_t)(n0 + ty + i) * K + k0 + tx] = __float2half(t[tx][ty + i]);
}

// fp32 -> fp16
__global__ void fconv_kernel(const float* __restrict__ X, __half* __restrict__ H)
{
    const size_t i = ((size_t)blockIdx.x * blockDim.x + threadIdx.x) * 4;
    float4 v = *(const float4*)(X + i);
    *(__half2*)(H + i)     = __floats2half2_rn(v.x, v.y);
    *(__half2*)(H + i + 2) = __floats2half2_rn(v.z, v.w);
}

// ---------------------------------------------------------------------------
// fp16 HMMA GEMM: C = act(A[M,K] @ W + bias) (+resid)
// CTA 128x256, BK=32, 256 thr (2x4 warps), warp tile 64x64, 3-stage cp.async.
// OUT: 0 = fp32 C (+resid), 1 = fp16 C.
// ACT: 0 none, 1 sigmoid, 2 5*sigmoid, 3 gelu, 4 resid-add
// smem rows padded to 40 halfs -> conflict-free ldmatrix + cp.async.
// ---------------------------------------------------------------------------
#define STG_ELEMS 15360
#define SMEM_BYTES (3 * STG_ELEMS * 2)

template <int ACT, int OUT>
__global__ void __launch_bounds__(256, 1)
mma_gemm(const __half* __restrict__ A, const __half* __restrict__ W,
         const float* __restrict__ bias, const float* __restrict__ resid,
         float* __restrict__ C, __half* __restrict__ Cf,
         int K, int ldc)
{
    extern __shared__ __half sm[];
    const int tid = threadIdx.x;
    const int wid = tid >> 5, lane = tid & 31;
    const int wm = wid & 1, wn = wid >> 1;
    const int group = lane >> 2, qp = lane & 3;
    const int bn = blockIdx.x * 256, bm = blockIdx.y * 128;
    const uint32_t smb = smem_u32(sm);
    const int lrow = tid >> 2, lg = tid & 3;

    const uint32_t offA = (uint32_t)((lane & 7) * 40 + ((lane >> 3) & 1) * 320 + (lane >> 4) * 8);
    const uint32_t offB = (uint32_t)((lane & 7) * 40 + ((lane >> 3) & 1) * 8 + (lane >> 4) * 320);

    float acc[4][8][4];
    #pragma unroll
    for (int i = 0; i < 4; i++)
        #pragma unroll
        for (int j = 0; j < 8; j++)
            #pragma unroll
            for (int p = 0; p < 4; p++) acc[i][j][p] = 0.0f;

    const int NT = K >> 5;

#define LOADT(kt, st) do {                                                    \
    _Pragma("unroll")                                                         \
    for (int rep = 0; rep < 2; rep++) {                                       \
        const int row = lrow + rep * 64;                                      \
        const size_t ga = (size_t)(bm + row) * K + (size_t)(kt) * 32 + lg * 8; \
        const uint32_t so = smb + 2u * (uint32_t)((st) * STG_ELEMS + row * 40 + lg * 8); \
        CP16(so, A + ga);                                                     \
    }                                                                         \
    _Pragma("unroll")                                                         \
    for (int rep = 0; rep < 4; rep++) {                                       \
        const int row = lrow + rep * 64;                                      \
        const size_t gb = (size_t)(bn + row) * K + (size_t)(kt) * 32 + lg * 8; \
        const uint32_t so = smb + 2u * (uint32_t)((st) * STG_ELEMS + 5120 + row * 40 + lg * 8); \
        CP16(so, W + gb);                                                     \
    }                                                                         \
} while (0)

    LOADT(0, 0); CP_COMMIT();
    if (NT > 1) { LOADT(1, 1); CP_COMMIT(); }

    for (int kt = 0; kt < NT; kt++) {
        const int st = kt % 3;
        if (kt + 1 < NT) CP_WAIT1(); else CP_WAIT0();
        __syncthreads();
        if (kt + 2 < NT) { LOADT(kt + 2, (kt + 2) % 3); CP_COMMIT(); }

        const uint32_t As = smb + 2u * (uint32_t)(st * STG_ELEMS);
        const uint32_t Bs = As + 2u * 5120u;
        #pragma unroll
        for (int ks = 0; ks < 2; ks++) {
            uint32_t ah[4][4], bb[4][4];
            #pragma unroll
            for (int i = 0; i < 4; i++) {
                const uint32_t ad = As + 2u * (uint32_t)((wm * 64 + i * 16) * 40 + ks * 16) + 2u * offA;
                LDSM4(ah[i][0], ah[i][1], ah[i][2], ah[i][3], ad);
            }
            #pragma unroll
            for (int jj = 0; jj < 4; jj++) {
                const uint32_t bd = Bs + 2u * (uint32_t)((wn * 64 + jj * 16) * 40 + ks * 16) + 2u * offB;
                LDSM4(bb[jj][0], bb[jj][1], bb[jj][2], bb[jj][3], bd);
            }
            #pragma unroll
            for (int i = 0; i < 4; i++)
                #pragma unroll
                for (int j = 0; j < 8; j++)
                    mma16816(acc[i][j], ah[i], &bb[j >> 1][(j & 1) * 2]);
        }
        __syncthreads();
    }

    // epilogue
    #pragma unroll
    for (int i = 0; i < 4; i++) {
        const int r0 = bm + wm * 64 + i * 16 + group;
        #pragma unroll
        for (int j = 0; j < 8; j++) {
            const int c = bn + wn * 64 + j * 8 + qp * 2;
            const float2 bv = *(const float2*)(bias + c);
            float v0 = acc[i][j][0] + bv.x;
            float v1 = acc[i][j][1] + bv.y;
            float v2 = acc[i][j][2] + bv.x;
            float v3 = acc[i][j][3] + bv.y;
            if (ACT == 4) {
                const float2 ra = *(const float2*)(resid + (size_t)r0 * ldc + c);
                const float2 rb = *(const float2*)(resid + (size_t)(r0 + 8) * ldc + c);
                v0 += ra.x; v1 += ra.y; v2 += rb.x; v3 += rb.y;
            } else {
                v0 = act_apply(v0, ACT); v1 = act_apply(v1, ACT);
                v2 = act_apply(v2, ACT); v3 = act_apply(v3, ACT);
            }
            if (OUT == 0) {
                *(float2*)(C + (size_t)r0 * ldc + c)       = make_float2(v0, v1);
                *(float2*)(C + (size_t)(r0 + 8) * ldc + c) = make_float2(v2, v3);
            } else {
                *(__half2*)(Cf + (size_t)r0 * ldc + c)       = __floats2half2_rn(v0, v1);
                *(__half2*)(Cf + (size_t)(r0 + 8) * ldc + c) = __floats2half2_rn(v2, v3);
            }
        }
    }
#undef LOADT
}

// ---------------- scan passes ----------------
__global__ void __launch_bounds__(Ddim)
passA_kernel(const float* __restrict__ x, const __half* __restrict__ omega,
             const __half* __restrict__ mag, const __half* __restrict__ gate,
             const __half* __restrict__ phii, const float* __restrict__ iscale,
             float4* __restrict__ csum)
{
    const int b = blockIdx.x / NC, c = blockIdx.x % NC, d = threadIdx.x;
    const float sc = fabsf(iscale[d]);
    size_t idx = ((size_t)b * Sdim + (size_t)c * CL) * Ddim + d;
    float rinc = 0.f, rmag = 0.f, rA = 0.f, rB = 0.f;
    #pragma unroll 4
    for (int s = 0; s < CL; s++, idx += Ddim) {
        float g = __half2float(gate[idx]), om = __half2float(omega[idx]);
        float m = __half2float(mag[idx]);
        float xv = x[idx], pi = __half2float(phii[idx]);
        rinc += g * om * sc;
        float sp, cp;
        sincosf(pi + rinc, &sp, &cp);
        float wc = m * xv;
        rA += wc * cp; rB += wc * sp; rmag += m;
    }
    csum[(size_t)blockIdx.x * Ddim + d] = make_float4(rinc, rmag, rA, rB);
}

__global__ void __launch_bounds__(Ddim)
passB_kernel(const float4* __restrict__ csum, float4* __restrict__ coff)
{
    const int b = blockIdx.x, d = threadIdx.x;
    float oi = 0.f, om = 0.f, omr = 0.f, omi = 0.f;
    #pragma unroll 4
    for (int c = 0; c < NC; c++) {
        const size_t i = ((size_t)b * NC + c) * Ddim + d;
        coff[i] = make_float4(oi, om, omr, omi);
        float4 s = csum[i];
        float st, ct;
        sincosf(oi, &st, &ct);
        omr += ct * s.z - st * s.w;
        omi += st * s.z + ct * s.w;
        oi += s.x; om += s.y;
    }
}

__global__ void __launch_bounds__(Ddim)
passC_kernel(const float* __restrict__ x, const __half* __restrict__ omega,
             const __half* __restrict__ mag, const __half* __restrict__ gate,
             const __half* __restrict__ phii, const __half* __restrict__ qoffp,
             const float* __restrict__ iscale, const float* __restrict__ lng,
             const float* __restrict__ lnb, const float4* __restrict__ coff,
             __half* __restrict__ ctx)
{
    __shared__ float2 warpred[16];
    __shared__ float2 bcast;
    const int b = blockIdx.x / NC, c = blockIdx.x % NC, d = threadIdx.x;
    const int lane = d & 31, wid = d >> 5;
    const float sc = fabsf(iscale[d]);
    const float g0 = lng[d], g1 = lng[Ddim + d], g2 = lng[2*Ddim+d], g3 = lng[3*Ddim+d];
    const float l0 = lnb[d], l1 = lnb[Ddim + d], l2 = lnb[2*Ddim+d], l3 = lnb[3*Ddim+d];

    float4 off = coff[(size_t)blockIdx.x * Ddim + d];
    float rinc = off.x, rmag = off.y, rmr = off.z, rmi = off.w;
    size_t idx   = ((size_t)b * Sdim + (size_t)c * CL) * Ddim + d;
    size_t cbase = ((size_t)b * Sdim + (size_t)c * CL) * (4 * Ddim) + d;

    for (int s = 0; s < CL; s++, idx += Ddim, cbase += 4 * Ddim) {
        float g = __half2float(gate[idx]), om = __half2float(omega[idx]);
        float m = __half2float(mag[idx]);
        float xv = x[idx], pi = __half2float(phii[idx]), qo = __half2float(qoffp[idx]);
        rinc += g * om * sc;
        float phi = pi + rinc;
        float sp, cp;
        sincosf(phi, &sp, &cp);
        float wc = m * xv;
        rmr += wc * cp; rmi += wc * sp; rmag += m;
        float rq = rsqrtf(rmag + 1e-8f);
        float mrv = rmr * rq, miv = rmi * rq;
        float sq, cq;
        sincosf(phi + qo, &sq, &cq);
        float v0 = xv * cp, v1 = xv * sp;
        float v2 = mrv * cq + miv * sq;
        float v3 = miv * cq - mrv * sq;

        float lsum = v0 + v1 + v2 + v3;
        float lss  = v0 * v0 + v1 * v1 + v2 * v2 + v3 * v3;
        #pragma unroll
        for (int o = 16; o > 0; o >>= 1) {
            lsum += __shfl_down_sync(0xffffffffu, lsum, o);
            lss  += __shfl_down_sync(0xffffffffu, lss, o);
        }
        if (lane == 0) warpred[wid] = make_float2(lsum, lss);
        __syncthreads();
        if (wid == 0) {
            float2 t = (lane < 16) ? warpred[lane] : make_float2(0.f, 0.f);
            #pragma unroll
            for (int o = 8; o > 0; o >>= 1) {
                t.x += __shfl_down_sync(0xffffffffu, t.x, o);
                t.y += __shfl_down_sync(0xffffffffu, t.y, o);
            }
            if (lane == 0) bcast = t;
        }
        __syncthreads();
        const float mean = bcast.x * (1.0f / 2048.0f);
        const float var  = bcast.y * (1.0f / 2048.0f) - mean * mean;
        const float rstd = rsqrtf(var + 1e-5f);
        ctx[cbase           ] = __float2half((v0 - mean) * rstd * g0 + l0);
        ctx[cbase + Ddim    ] = __float2half((v1 - mean) * rstd * g1 + l1);
        ctx[cbase + 2 * Ddim] = __float2half((v2 - mean) * rstd * g2 + l2);
        ctx[cbase + 3 * Ddim] = __float2half((v3 - mean) * rstd * g3 + l3);
    }
}

// ---------------- launch ----------------
extern "C" void kernel_launch(void* const* d_in, const int* in_sizes, int n_in,
                              void* d_out, int out_size)
{
    const float* x       = (const float*)d_in[0];
    const float* W_omega = (const float*)d_in[1];
    const float* b_omega = (const float*)d_in[2];
    const float* W_p1    = (const float*)d_in[3];
    const float* b_p1    = (const float*)d_in[4];
    const float* W_p2    = (const float*)d_in[5];
    const float* b_p2    = (const float*)d_in[6];
    const float* W_gate  = (const float*)d_in[7];
    const float* b_gate  = (const float*)d_in[8];
    const float* iscale  = (const float*)d_in[9];
    const float* W_mag   = (const float*)d_in[10];
    const float* b_mag   = (const float*)d_in[11];
    const float* W_qoff  = (const float*)d_in[12];
    const float* b_qoff  = (const float*)d_in[13];
    const float* ln_g    = (const float*)d_in[14];
    const float* ln_b    = (const float*)d_in[15];
    const float* W_o1    = (const float*)d_in[16];
    const float* b_o1    = (const float*)d_in[17];
    const float* W_o2    = (const float*)d_in[18];
    const float* b_o2    = (const float*)d_in[19];
    float* out = (float*)d_out;

    __half *p_omega, *p_mag, *p_gate, *p_qoff, *p_phii;
    __half *p_xf, *p_p1f, *p_ctxf, *p_hf, *p_wf;
    float4 *p_csum, *p_coff;
    cudaGetSymbolAddress((void**)&p_omega, g_omega);
    cudaGetSymbolAddress((void**)&p_mag,   g_mag);
    cudaGetSymbolAddress((void**)&p_gate,  g_gate);
    cudaGetSymbolAddress((void**)&p_qoff,  g_qoff);
    cudaGetSymbolAddress((void**)&p_phii,  g_phii);
    cudaGetSymbolAddress((void**)&p_xf,    g_xf);
    cudaGetSymbolAddress((void**)&p_p1f,   g_p1f);
    cudaGetSymbolAddress((void**)&p_ctxf,  g_ctxf);
    cudaGetSymbolAddress((void**)&p_hf,    g_hf);
    cudaGetSymbolAddress((void**)&p_wf,    g_wf);
    cudaGetSymbolAddress((void**)&p_csum,  g_csum);
    cudaGetSymbolAddress((void**)&p_coff,  g_coff);

    cudaFuncSetAttribute(mma_gemm<0,1>, cudaFuncAttributeMaxDynamicSharedMemorySize, SMEM_BYTES);
    cudaFuncSetAttribute(mma_gemm<1,1>, cudaFuncAttributeMaxDynamicSharedMemorySize, SMEM_BYTES);
    cudaFuncSetAttribute(mma_gemm<2,1>, cudaFuncAttributeMaxDynamicSharedMemorySize, SMEM_BYTES);
    cudaFuncSetAttribute(mma_gemm<3,1>, cudaFuncAttributeMaxDynamicSharedMemorySize, SMEM_BYTES);
    cudaFuncSetAttribute(mma_gemm<4,0>, cudaFuncAttributeMaxDynamicSharedMemorySize, SMEM_BYTES);

    const dim3 tb(32, 8);
    wconv_kernel<<<dim3(16, 16), tb>>>(W_omega, p_wf + OFF_OM,   512, 512);
    wconv_kernel<<<dim3(16, 16), tb>>>(W_mag,   p_wf + OFF_MAG,  512, 512);
    wconv_kernel<<<dim3(16, 16), tb>>>(W_gate,  p_wf + OFF_GATE, 512, 512);
    wconv_kernel<<<dim3(16, 16), tb>>>(W_qoff,  p_wf + OFF_QOFF, 512, 512);
    wconv_kernel<<<dim3(16, 16), tb>>>(W_p1,    p_wf + OFF_P1,   512, 512);
    wconv_kernel<<<dim3(16, 16), tb>>>(W_p2,    p_wf + OFF_P2,   512, 512);
    wconv_kernel<<<dim3(32, 64), tb>>>(W_o1,    p_wf + OFF_O1,   2048, 1024);
    wconv_kernel<<<dim3(16, 32), tb>>>(W_o2,    p_wf + OFF_O2,   1024, 512);

    fconv_kernel<<<(size_t)Mrows * Ddim / 4 / 256, 256>>>(x, p_xf);

    const dim3 blk(256);
    const dim3 gP(2, Mrows / 128);
    const dim3 gO1(4, Mrows / 128);
    const dim3 gO2(2, Mrows / 128);

    mma_gemm<0,1><<<gP, blk, SMEM_BYTES>>>(p_xf, p_wf + OFF_OM,   b_omega, 0, 0, p_omega, 512, 512);
    mma_gemm<2,1><<<gP, blk, SMEM_BYTES>>>(p_xf, p_wf + OFF_MAG,  b_mag,   0, 0, p_mag,   512, 512);
    mma_gemm<1,1><<<gP, blk, SMEM_BYTES>>>(p_xf, p_wf + OFF_GATE, b_gate,  0, 0, p_gate,  512, 512);
    mma_gemm<0,1><<<gP, blk, SMEM_BYTES>>>(p_xf, p_wf + OFF_QOFF, b_qoff,  0, 0, p_qoff,  512, 512);
    mma_gemm<3,1><<<gP, blk, SMEM_BYTES>>>(p_xf, p_wf + OFF_P1,   b_p1,    0, 0, p_p1f,   512, 512);
    mma_gemm<0,1><<<gP, blk, SMEM_BYTES>>>(p_p1f, p_wf + OFF_P2,  b_p2,    0, 0, p_phii,  512, 512);

    passA_kernel<<<Bdim * NC, Ddim>>>(x, p_omega, p_mag, p_gate, p_phii, iscale, p_csum);
    passB_kernel<<<Bdim, Ddim>>>(p_csum, p_coff);
    passC_kernel<<<Bdim * NC, Ddim>>>(x, p_omega, p_mag, p_gate, p_phii, p_qoff,
                                      iscale, ln_g, ln_b, p_coff, p_ctxf);

    mma_gemm<3,1><<<gO1, blk, SMEM_BYTES>>>(p_ctxf, p_wf + OFF_O1, b_o1, 0, 0, p_hf, 2048, 1024);
    mma_gemm<4,0><<<gO2, blk, SMEM_BYTES>>>(p_hf,   p_wf + OFF_O2, b_o2, x, out, 0, 1024, 512);
}

// round 7
// speedup vs baseline: 1.0970x; 1.0970x over previous
#include <cuda_runtime.h>
#include <cuda_fp16.h>
#include <math.h>
#include <stdint.h>

#define Bdim 8
#define Sdim 4096
#define Ddim 512
#define Mrows (Bdim * Sdim)
#define NC 32
#define CL (Sdim / NC)
#define NPROJ 2560   /* 5 fused projections */

// ---------------- scratch ----------------
__device__ __half g_proj[(size_t)Mrows * NPROJ];   // omega|mag|gate|qoff|p1
__device__ __half g_phii[(size_t)Mrows * Ddim];
__device__ __half g_xf  [(size_t)Mrows * Ddim];
__device__ __half g_ctxf[(size_t)Mrows * 4 * Ddim];
__device__ __half g_hf  [(size_t)Mrows * 2 * Ddim];
__device__ float4 g_csum[Bdim * NC * Ddim];
__device__ float4 g_coff[Bdim * NC * Ddim];
__device__ __half g_wf[4194304];
__device__ float  g_bcat[NPROJ];

#define OFF_OM   0
#define OFF_MAG  262144
#define OFF_GATE 524288
#define OFF_QOFF 786432
#define OFF_P1   1048576
#define OFF_P2   1310720
#define OFF_O1   1572864
#define OFF_O2   3670016

// ---------------- helpers ----------------
__device__ __forceinline__ uint32_t smem_u32(const void* p) {
    uint32_t a;
    asm("{ .reg .u64 t; cvta.to.shared.u64 t, %1; cvt.u32.u64 %0, t; }" : "=r"(a) : "l"(p));
    return a;
}
#define CP16(so, gp) \
    asm volatile("cp.async.cg.shared.global [%0], [%1], 16;" :: "r"(so), "l"(gp) : "memory")
#define CP_COMMIT() asm volatile("cp.async.commit_group;" ::: "memory")
#define CP_WAIT1()  asm volatile("cp.async.wait_group 1;" ::: "memory")
#define CP_WAIT0()  asm volatile("cp.async.wait_group 0;" ::: "memory")

#define LDSM4(r0, r1, r2, r3, a)                                              \
    asm volatile("ldmatrix.sync.aligned.m8n8.x4.shared.b16 {%0,%1,%2,%3}, [%4];" \
                 : "=r"(r0), "=r"(r1), "=r"(r2), "=r"(r3) : "r"(a))

__device__ __forceinline__ void mma16816(float* c, const uint32_t* a, const uint32_t* b) {
    asm volatile(
        "mma.sync.aligned.m16n8k16.row.col.f32.f16.f16.f32 "
        "{%0,%1,%2,%3}, {%4,%5,%6,%7}, {%8,%9}, {%0,%1,%2,%3};"
        : "+f"(c[0]), "+f"(c[1]), "+f"(c[2]), "+f"(c[3])
        : "r"(a[0]), "r"(a[1]), "r"(a[2]), "r"(a[3]), "r"(b[0]), "r"(b[1]));
}

__device__ __forceinline__ float act_apply(float v, int ACT) {
    if (ACT == 1) return 1.0f / (1.0f + expf(-v));
    if (ACT == 2) return 5.0f / (1.0f + expf(-v));
    if (ACT == 3) return 0.5f * v * (1.0f + erff(v * 0.70710678118654752f));
    return v;
}

// W[K,N] fp32 -> T[N,K] fp16 (transpose + convert)
__global__ void wconv_kernel(const float* __restrict__ W, __half* __restrict__ T,
                             int K, int N)
{
    __shared__ float t[32][33];
    const int tx = threadIdx.x, ty = threadIdx.y;
    const int n0 = blockIdx.x * 32, k0 = blockIdx.y * 32;
    #pragma unroll
    for (int i = 0; i < 32; i += 8)
        t[ty + i][tx] = W[(size_t)(k0 + ty + i) * N + n0 + tx];
    __syncthreads();
    #pragma unroll
    for (int i = 0; i < 32; i += 8)
        T[(size_t)(n0 + ty + i) * K + k0 + tx] = __float2half(t[tx][ty + i]);
}

// fp32 -> fp16
__global__ void fconv_kernel(const float* __restrict__ X, __half* __restrict__ H)
{
    const size_t i = ((size_t)blockIdx.x * blockDim.x + threadIdx.x) * 4;
    float4 v = *(const float4*)(X + i);
    *(__half2*)(H + i)     = __floats2half2_rn(v.x, v.y);
    *(__half2*)(H + i + 2) = __floats2half2_rn(v.z, v.w);
}

// gather 5 bias vectors into one [2560]
__global__ void bcat_kernel(const float* b0, const float* b1, const float* b2,
                            const float* b3, const float* b4, float* out)
{
    const int i = blockIdx.x * blockDim.x + threadIdx.x;
    if (i >= NPROJ) return;
    const int seg = i >> 9, d = i & 511;
    const float* src = (seg == 0) ? b0 : (seg == 1) ? b1 : (seg == 2) ? b2
                                    : (seg == 3) ? b3 : b4;
    out[i] = src[d];
}

// ---------------------------------------------------------------------------
// fp16 HMMA GEMM: C = act(A[M,K](lda) @ W + bias) (+resid)
// CTA 128x128, BK=32, 256 thr, warp 64x32, 3-stage cp.async (R5 proven cfg).
// ACT: 0 none, 1 sig, 2 5sig, 3 gelu, 4 resid-add, 5 segmented (bn>>9).
// OUT: 0 fp32, 1 fp16.
// ---------------------------------------------------------------------------
#define STG_ELEMS 10240
#define SMEM_BYTES (3 * STG_ELEMS * 2)

template <int ACT, int OUT>
__global__ void __launch_bounds__(256)
mma_gemm(const __half* __restrict__ A, const __half* __restrict__ W,
         const float* __restrict__ bias, const float* __restrict__ resid,
         float* __restrict__ C, __half* __restrict__ Cf,
         int K, int lda, int ldc)
{
    extern __shared__ __half sm[];
    const int tid = threadIdx.x;
    const int wid = tid >> 5, lane = tid & 31;
    const int wm = wid & 1, wn = wid >> 1;
    const int group = lane >> 2, qp = lane & 3;
    const int bn = blockIdx.x * 128, bm = blockIdx.y * 128;
    const uint32_t smb = smem_u32(sm);
    const int lrow = tid >> 2, lg = tid & 3;

    const uint32_t offA = (uint32_t)((lane & 7) * 40 + ((lane >> 3) & 1) * 320 + (lane >> 4) * 8);
    const uint32_t offB = (uint32_t)((lane & 7) * 40 + ((lane >> 3) & 1) * 8 + (lane >> 4) * 320);

    float acc[4][4][4];
    #pragma unroll
    for (int i = 0; i < 4; i++)
        #pragma unroll
        for (int j = 0; j < 4; j++)
            #pragma unroll
            for (int p = 0; p < 4; p++) acc[i][j][p] = 0.0f;

    const int NT = K >> 5;

#define LOADT(kt, st) do {                                                    \
    _Pragma("unroll")                                                         \
    for (int rep = 0; rep < 2; rep++) {                                       \
        const int row = lrow + rep * 64;                                      \
        const size_t ga = (size_t)(bm + row) * lda + (size_t)(kt) * 32 + lg * 8; \
        const size_t gb = (size_t)(bn + row) * K + (size_t)(kt) * 32 + lg * 8; \
        const uint32_t so = smb + 2u * (uint32_t)((st) * STG_ELEMS + row * 40 + lg * 8); \
        CP16(so, A + ga);                                                     \
        CP16(so + 2 * 5120, W + gb);                                          \
    }                                                                         \
} while (0)

    LOADT(0, 0); CP_COMMIT();
    if (NT > 1) { LOADT(1, 1); CP_COMMIT(); }

    for (int kt = 0; kt < NT; kt++) {
        const int st = kt % 3;
        if (kt + 1 < NT) CP_WAIT1(); else CP_WAIT0();
        __syncthreads();
        if (kt + 2 < NT) { LOADT(kt + 2, (kt + 2) % 3); CP_COMMIT(); }

        const uint32_t As = smb + 2u * (uint32_t)(st * STG_ELEMS);
        const uint32_t Bs = As + 2u * 5120u;
        #pragma unroll
        for (int ks = 0; ks < 2; ks++) {
            uint32_t ah[4][4], bb[2][4];
            #pragma unroll
            for (int i = 0; i < 4; i++) {
                const uint32_t ad = As + 2u * (uint32_t)((wm * 64 + i * 16) * 40 + ks * 16) + 2u * offA;
                LDSM4(ah[i][0], ah[i][1], ah[i][2], ah[i][3], ad);
            }
            #pragma unroll
            for (int jj = 0; jj < 2; jj++) {
                const uint32_t bd = Bs + 2u * (uint32_t)((wn * 32 + jj * 16) * 40 + ks * 16) + 2u * offB;
                LDSM4(bb[jj][0], bb[jj][1], bb[jj][2], bb[jj][3], bd);
            }
            #pragma unroll
            for (int i = 0; i < 4; i++)
                #pragma unroll
                for (int j = 0; j < 4; j++)
                    mma16816(acc[i][j], ah[i], &bb[j >> 1][(j & 1) * 2]);
        }
        __syncthreads();
    }

    // epilogue
    int act = ACT;
    if (ACT == 5) {
        const int seg = bn >> 9;       // uniform per CTA (N-tile 128 within 512-seg)
        act = (seg == 1) ? 2 : (seg == 2) ? 1 : (seg == 4) ? 3 : 0;
    }
    #pragma unroll
    for (int i = 0; i < 4; i++) {
        const int r0 = bm + wm * 64 + i * 16 + group;
        #pragma unroll
        for (int j = 0; j < 4; j++) {
            const int c = bn + wn * 32 + j * 8 + qp * 2;
            const float2 bv = *(const float2*)(bias + c);
            float v0 = acc[i][j][0] + bv.x;
            float v1 = acc[i][j][1] + bv.y;
            float v2 = acc[i][j][2] + bv.x;
            float v3 = acc[i][j][3] + bv.y;
            if (ACT == 4) {
                const float2 ra = *(const float2*)(resid + (size_t)r0 * ldc + c);
                const float2 rb = *(const float2*)(resid + (size_t)(r0 + 8) * ldc + c);
                v0 += ra.x; v1 += ra.y; v2 += rb.x; v3 += rb.y;
            } else {
                v0 = act_apply(v0, act); v1 = act_apply(v1, act);
                v2 = act_apply(v2, act); v3 = act_apply(v3, act);
            }
            if (OUT == 0) {
                *(float2*)(C + (size_t)r0 * ldc + c)       = make_float2(v0, v1);
                *(float2*)(C + (size_t)(r0 + 8) * ldc + c) = make_float2(v2, v3);
            } else {
                *(__half2*)(Cf + (size_t)r0 * ldc + c)       = __floats2half2_rn(v0, v1);
                *(__half2*)(Cf + (size_t)(r0 + 8) * ldc + c) = __floats2half2_rn(v2, v3);
            }
        }
    }
#undef LOADT
}

// ---------------- scan passes ----------------
// proj row layout: [omega(0) | mag(512) | gate(1024) | qoff(1536) | p1(2048)]
__global__ void __launch_bounds__(Ddim)
passA_kernel(const float* __restrict__ x, const __half* __restrict__ proj,
             const __half* __restrict__ phii, const float* __restrict__ iscale,
             float4* __restrict__ csum)
{
    const int b = blockIdx.x / NC, c = blockIdx.x % NC, d = threadIdx.x;
    const float sc = fabsf(iscale[d]);
    size_t row = (size_t)b * Sdim + (size_t)c * CL;
    size_t idx = row * Ddim + d;
    size_t pidx = row * NPROJ + d;
    float rinc = 0.f, rmag = 0.f, rA = 0.f, rB = 0.f;
    #pragma unroll 2
    for (int s = 0; s < CL; s++, idx += Ddim, pidx += NPROJ) {
        float om = __half2float(proj[pidx]);
        float m  = __half2float(proj[pidx + 512]);
        float g  = __half2float(proj[pidx + 1024]);
        float xv = x[idx], pi = __half2float(phii[idx]);
        rinc += g * om * sc;
        float sp, cp;
        sincosf(pi + rinc, &sp, &cp);
        float wc = m * xv;
        rA += wc * cp; rB += wc * sp; rmag += m;
    }
    csum[(size_t)blockIdx.x * Ddim + d] = make_float4(rinc, rmag, rA, rB);
}

__global__ void __launch_bounds__(Ddim)
passB_kernel(const float4* __restrict__ csum, float4* __restrict__ coff)
{
    const int b = blockIdx.x, d = threadIdx.x;
    float oi = 0.f, om = 0.f, omr = 0.f, omi = 0.f;
    #pragma unroll 4
    for (int c = 0; c < NC; c++) {
        const size_t i = ((size_t)b * NC + c) * Ddim + d;
        coff[i] = make_float4(oi, om, omr, omi);
        float4 s = csum[i];
        float st, ct;
        sincosf(oi, &st, &ct);
        omr += ct * s.z - st * s.w;
        omi += st * s.z + ct * s.w;
        oi += s.x; om += s.y;
    }
}

__global__ void __launch_bounds__(Ddim)
passC_kernel(const float* __restrict__ x, const __half* __restrict__ proj,
             const __half* __restrict__ phii,
             const float* __restrict__ iscale, const float* __restrict__ lng,
             const float* __restrict__ lnb, const float4* __restrict__ coff,
             __half* __restrict__ ctx)
{
    __shared__ float2 warpred[16];
    __shared__ float2 bcast;
    const int b = blockIdx.x / NC, c = blockIdx.x % NC, d = threadIdx.x;
    const int lane = d & 31, wid = d >> 5;
    const float sc = fabsf(iscale[d]);
    const float g0 = lng[d], g1 = lng[Ddim + d], g2 = lng[2*Ddim+d], g3 = lng[3*Ddim+d];
    const float l0 = lnb[d], l1 = lnb[Ddim + d], l2 = lnb[2*Ddim+d], l3 = lnb[3*Ddim+d];

    float4 off = coff[(size_t)blockIdx.x * Ddim + d];
    float rinc = off.x, rmag = off.y, rmr = off.z, rmi = off.w;
    size_t row   = (size_t)b * Sdim + (size_t)c * CL;
    size_t idx   = row * Ddim + d;
    size_t pidx  = row * NPROJ + d;
    size_t cbase = row * (4 * Ddim) + d;

    for (int s = 0; s < CL; s++, idx += Ddim, pidx += NPROJ, cbase += 4 * Ddim) {
        float om = __half2float(proj[pidx]);
        float m  = __half2float(proj[pidx + 512]);
        float g  = __half2float(proj[pidx + 1024]);
        float qo = __half2float(proj[pidx + 1536]);
        float xv = x[idx], pi = __half2float(phii[idx]);
        rinc += g * om * sc;
        float phi = pi + rinc;
        float sp, cp;
        sincosf(phi, &sp, &cp);
        float wc = m * xv;
        rmr += wc * cp; rmi += wc * sp; rmag += m;
        float rq = rsqrtf(rmag + 1e-8f);
        float mrv = rmr * rq, miv = rmi * rq;
        float sq, cq;
        sincosf(phi + qo, &sq, &cq);
        float v0 = xv * cp, v1 = xv * sp;
        float v2 = mrv * cq + miv * sq;
        float v3 = miv * cq - mrv * sq;

        float lsum = v0 + v1 + v2 + v3;
        float lss  = v0 * v0 + v1 * v1 + v2 * v2 + v3 * v3;
        #pragma unroll
        for (int o = 16; o > 0; o >>= 1) {
            lsum += __shfl_down_sync(0xffffffffu, lsum, o);
            lss  += __shfl_down_sync(0xffffffffu, lss, o);
        }
        if (lane == 0) warpred[wid] = make_float2(lsum, lss);
        __syncthreads();
        if (wid == 0) {
            float2 t = (lane < 16) ? warpred[lane] : make_float2(0.f, 0.f);
            #pragma unroll
            for (int o = 8; o > 0; o >>= 1) {
                t.x += __shfl_down_sync(0xffffffffu, t.x, o);
                t.y += __shfl_down_sync(0xffffffffu, t.y, o);
            }
            if (lane == 0) bcast = t;
        }
        __syncthreads();
        const float mean = bcast.x * (1.0f / 2048.0f);
        const float var  = bcast.y * (1.0f / 2048.0f) - mean * mean;
        const float rstd = rsqrtf(var + 1e-5f);
        ctx[cbase           ] = __float2half((v0 - mean) * rstd * g0 + l0);
        ctx[cbase + Ddim    ] = __float2half((v1 - mean) * rstd * g1 + l1);
        ctx[cbase + 2 * Ddim] = __float2half((v2 - mean) * rstd * g2 + l2);
        ctx[cbase + 3 * Ddim] = __float2half((v3 - mean) * rstd * g3 + l3);
    }
}

// ---------------- launch ----------------
extern "C" void kernel_launch(void* const* d_in, const int* in_sizes, int n_in,
                              void* d_out, int out_size)
{
    const float* x       = (const float*)d_in[0];
    const float* W_omega = (const float*)d_in[1];
    const float* b_omega = (const float*)d_in[2];
    const float* W_p1    = (const float*)d_in[3];
    const float* b_p1    = (const float*)d_in[4];
    const float* W_p2    = (const float*)d_in[5];
    const float* b_p2    = (const float*)d_in[6];
    const float* W_gate  = (const float*)d_in[7];
    const float* b_gate  = (const float*)d_in[8];
    const float* iscale  = (const float*)d_in[9];
    const float* W_mag   = (const float*)d_in[10];
    const float* b_mag   = (const float*)d_in[11];
    const float* W_qoff  = (const float*)d_in[12];
    const float* b_qoff  = (const float*)d_in[13];
    const float* ln_g    = (const float*)d_in[14];
    const float* ln_b    = (const float*)d_in[15];
    const float* W_o1    = (const float*)d_in[16];
    const float* b_o1    = (const float*)d_in[17];
    const float* W_o2    = (const float*)d_in[18];
    const float* b_o2    = (const float*)d_in[19];
    float* out = (float*)d_out;

    __half *p_proj, *p_phii, *p_xf, *p_ctxf, *p_hf, *p_wf;
    float *p_bcat;
    float4 *p_csum, *p_coff;
    cudaGetSymbolAddress((void**)&p_proj,  g_proj);
    cudaGetSymbolAddress((void**)&p_phii,  g_phii);
    cudaGetSymbolAddress((void**)&p_xf,    g_xf);
    cudaGetSymbolAddress((void**)&p_ctxf,  g_ctxf);
    cudaGetSymbolAddress((void**)&p_hf,    g_hf);
    cudaGetSymbolAddress((void**)&p_wf,    g_wf);
    cudaGetSymbolAddress((void**)&p_bcat,  g_bcat);
    cudaGetSymbolAddress((void**)&p_csum,  g_csum);
    cudaGetSymbolAddress((void**)&p_coff,  g_coff);

    cudaFuncSetAttribute(mma_gemm<5,1>, cudaFuncAttributeMaxDynamicSharedMemorySize, SMEM_BYTES);
    cudaFuncSetAttribute(mma_gemm<0,1>, cudaFuncAttributeMaxDynamicSharedMemorySize, SMEM_BYTES);
    cudaFuncSetAttribute(mma_gemm<3,1>, cudaFuncAttributeMaxDynamicSharedMemorySize, SMEM_BYTES);
    cudaFuncSetAttribute(mma_gemm<4,0>, cudaFuncAttributeMaxDynamicSharedMemorySize, SMEM_BYTES);

    const dim3 tb(32, 8);
    wconv_kernel<<<dim3(16, 16), tb>>>(W_omega, p_wf + OFF_OM,   512, 512);
    wconv_kernel<<<dim3(16, 16), tb>>>(W_mag,   p_wf + OFF_MAG,  512, 512);
    wconv_kernel<<<dim3(16, 16), tb>>>(W_gate,  p_wf + OFF_GATE, 512, 512);
    wconv_kernel<<<dim3(16, 16), tb>>>(W_qoff,  p_wf + OFF_QOFF, 512, 512);
    wconv_kernel<<<dim3(16, 16), tb>>>(W_p1,    p_wf + OFF_P1,   512, 512);
    wconv_kernel<<<dim3(16, 16), tb>>>(W_p2,    p_wf + OFF_P2,   512, 512);
    wconv_kernel<<<dim3(32, 64), tb>>>(W_o1,    p_wf + OFF_O1,   2048, 1024);
    wconv_kernel<<<dim3(16, 32), tb>>>(W_o2,    p_wf + OFF_O2,   1024, 512);

    fconv_kernel<<<(size_t)Mrows * Ddim / 4 / 256, 256>>>(x, p_xf);
    bcat_kernel<<<(NPROJ + 255) / 256, 256>>>(b_omega, b_mag, b_gate, b_qoff, b_p1, p_bcat);

    const dim3 blk(256);

    // Fused 5-projection GEMM: [M,512] @ [512,2560] -> proj (segmented act)
    mma_gemm<5,1><<<dim3(NPROJ / 128, Mrows / 128), blk, SMEM_BYTES>>>(
        p_xf, p_wf + OFF_OM, p_bcat, 0, 0, p_proj, 512, 512, NPROJ);

    // p2: phi_init = p1seg @ W_p2 + b_p2  (A strided out of proj buffer)
    mma_gemm<0,1><<<dim3(4, Mrows / 128), blk, SMEM_BYTES>>>(
        p_proj + 2048, p_wf + OFF_P2, b_p2, 0, 0, p_phii, 512, NPROJ, 512);

    passA_kernel<<<Bdim * NC, Ddim>>>(x, p_proj, p_phii, iscale, p_csum);
    passB_kernel<<<Bdim, Ddim>>>(p_csum, p_coff);
    passC_kernel<<<Bdim * NC, Ddim>>>(x, p_proj, p_phii, iscale, ln_g, ln_b,
                                      p_coff, p_ctxf);

    mma_gemm<3,1><<<dim3(8, Mrows / 128), blk, SMEM_BYTES>>>(
        p_ctxf, p_wf + OFF_O1, b_o1, 0, 0, p_hf, 2048, 2048, 1024);
    mma_gemm<4,0><<<dim3(4, Mrows / 128), blk, SMEM_BYTES>>>(
        p_hf, p_wf + OFF_O2, b_o2, x, out, 0, 1024, 1024, 512);
}

// round 8
// speedup vs baseline: 1.1551x; 1.0530x over previous
#include <cuda_runtime.h>
#include <cuda_fp16.h>
#include <math.h>
#include <stdint.h>

#define Bdim 8
#define Sdim 4096
#define Ddim 512
#define Mrows (Bdim * Sdim)
#define NC 64
#define CL (Sdim / NC)
#define NPROJ 2560   /* 5 fused projections */

// ---------------- scratch ----------------
__device__ __half g_proj[(size_t)Mrows * NPROJ];   // omega|mag|gate|qoff|p1
__device__ __half g_phii[(size_t)Mrows * Ddim];
__device__ __half g_xf  [(size_t)Mrows * Ddim];
__device__ __half g_ctxf[(size_t)Mrows * 4 * Ddim];
__device__ __half g_hf  [(size_t)Mrows * 2 * Ddim];
__device__ float4 g_csum[Bdim * NC * Ddim];
__device__ float4 g_coff[Bdim * NC * Ddim];
__device__ __half g_wf[4194304];
__device__ float  g_bcat[NPROJ];

#define OFF_OM   0
#define OFF_MAG  262144
#define OFF_GATE 524288
#define OFF_QOFF 786432
#define OFF_P1   1048576
#define OFF_P2   1310720
#define OFF_O1   1572864
#define OFF_O2   3670016

// ---------------- helpers ----------------
__device__ __forceinline__ uint32_t smem_u32(const void* p) {
    uint32_t a;
    asm("{ .reg .u64 t; cvta.to.shared.u64 t, %1; cvt.u32.u64 %0, t; }" : "=r"(a) : "l"(p));
    return a;
}
#define CP16(so, gp) \
    asm volatile("cp.async.cg.shared.global [%0], [%1], 16;" :: "r"(so), "l"(gp) : "memory")
#define CP_COMMIT() asm volatile("cp.async.commit_group;" ::: "memory")
#define CP_WAIT1()  asm volatile("cp.async.wait_group 1;" ::: "memory")
#define CP_WAIT0()  asm volatile("cp.async.wait_group 0;" ::: "memory")

#define LDSM4(r0, r1, r2, r3, a)                                              \
    asm volatile("ldmatrix.sync.aligned.m8n8.x4.shared.b16 {%0,%1,%2,%3}, [%4];" \
                 : "=r"(r0), "=r"(r1), "=r"(r2), "=r"(r3) : "r"(a))

__device__ __forceinline__ void mma16816(float* c, const uint32_t* a, const uint32_t* b) {
    asm volatile(
        "mma.sync.aligned.m16n8k16.row.col.f32.f16.f16.f32 "
        "{%0,%1,%2,%3}, {%4,%5,%6,%7}, {%8,%9}, {%0,%1,%2,%3};"
        : "+f"(c[0]), "+f"(c[1]), "+f"(c[2]), "+f"(c[3])
        : "r"(a[0]), "r"(a[1]), "r"(a[2]), "r"(a[3]), "r"(b[0]), "r"(b[1]));
}

__device__ __forceinline__ float act_apply(float v, int ACT) {
    if (ACT == 1) return 1.0f / (1.0f + __expf(-v));
    if (ACT == 2) return 5.0f / (1.0f + __expf(-v));
    if (ACT == 3) return 0.5f * v * (1.0f + erff(v * 0.70710678118654752f));
    return v;
}

// Batched: six 512x512 W[K,N] fp32 -> T[N,K] fp16 (transpose + convert)
__global__ void wconv6_kernel(const float* __restrict__ W0, const float* __restrict__ W1,
                              const float* __restrict__ W2, const float* __restrict__ W3,
                              const float* __restrict__ W4, const float* __restrict__ W5,
                              __half* __restrict__ T)
{
    __shared__ float t[32][33];
    const int z = blockIdx.z;
    const float* W = (z == 0) ? W0 : (z == 1) ? W1 : (z == 2) ? W2
                   : (z == 3) ? W3 : (z == 4) ? W4 : W5;
    __half* Tz = T + (size_t)z * 262144;
    const int tx = threadIdx.x, ty = threadIdx.y;
    const int n0 = blockIdx.x * 32, k0 = blockIdx.y * 32;
    #pragma unroll
    for (int i = 0; i < 32; i += 8)
        t[ty + i][tx] = W[(size_t)(k0 + ty + i) * 512 + n0 + tx];
    __syncthreads();
    #pragma unroll
    for (int i = 0; i < 32; i += 8)
        Tz[(size_t)(n0 + ty + i) * 512 + k0 + tx] = __float2half(t[tx][ty + i]);
}

__global__ void wconv_kernel(const float* __restrict__ W, __half* __restrict__ T,
                             int K, int N)
{
    __shared__ float t[32][33];
    const int tx = threadIdx.x, ty = threadIdx.y;
    const int n0 = blockIdx.x * 32, k0 = blockIdx.y * 32;
    #pragma unroll
    for (int i = 0; i < 32; i += 8)
        t[ty + i][tx] = W[(size_t)(k0 + ty + i) * N + n0 + tx];
    __syncthreads();
    #pragma unroll
    for (int i = 0; i < 32; i += 8)
        T[(size_t)(n0 + ty + i) * K + k0 + tx] = __float2half(t[tx][ty + i]);
}

// fp32 -> fp16
__global__ void fconv_kernel(const float* __restrict__ X, __half* __restrict__ H)
{
    const size_t i = ((size_t)blockIdx.x * blockDim.x + threadIdx.x) * 4;
    float4 v = *(const float4*)(X + i);
    *(__half2*)(H + i)     = __floats2half2_rn(v.x, v.y);
    *(__half2*)(H + i + 2) = __floats2half2_rn(v.z, v.w);
}

// gather 5 bias vectors into one [2560]
__global__ void bcat_kernel(const float* b0, const float* b1, const float* b2,
                            const float* b3, const float* b4, float* out)
{
    const int i = blockIdx.x * blockDim.x + threadIdx.x;
    if (i >= NPROJ) return;
    const int seg = i >> 9, d = i & 511;
    const float* src = (seg == 0) ? b0 : (seg == 1) ? b1 : (seg == 2) ? b2
                                    : (seg == 3) ? b3 : b4;
    out[i] = src[d];
}

// ---------------------------------------------------------------------------
// fp16 HMMA GEMM: C = act(A[M,K](lda) @ W + bias) (+resid)
// CTA 128x128, BK=32, 256 thr, warp 64x32, 3-stage cp.async (proven cfg).
// ACT: 0 none, 1 sig, 2 5sig, 3 gelu, 4 resid-add, 5 segmented (bn>>9).
// OUT: 0 fp32, 1 fp16.
// ---------------------------------------------------------------------------
#define STG_ELEMS 10240
#define SMEM_BYTES (3 * STG_ELEMS * 2)

template <int ACT, int OUT>
__global__ void __launch_bounds__(256)
mma_gemm(const __half* __restrict__ A, const __half* __restrict__ W,
         const float* __restrict__ bias, const float* __restrict__ resid,
         float* __restrict__ C, __half* __restrict__ Cf,
         int K, int lda, int ldc)
{
    extern __shared__ __half sm[];
    const int tid = threadIdx.x;
    const int wid = tid >> 5, lane = tid & 31;
    const int wm = wid & 1, wn = wid >> 1;
    const int group = lane >> 2, qp = lane & 3;
    const int bn = blockIdx.x * 128, bm = blockIdx.y * 128;
    const uint32_t smb = smem_u32(sm);
    const int lrow = tid >> 2, lg = tid & 3;

    const uint32_t offA = (uint32_t)((lane & 7) * 40 + ((lane >> 3) & 1) * 320 + (lane >> 4) * 8);
    const uint32_t offB = (uint32_t)((lane & 7) * 40 + ((lane >> 3) & 1) * 8 + (lane >> 4) * 320);

    float acc[4][4][4];
    #pragma unroll
    for (int i = 0; i < 4; i++)
        #pragma unroll
        for (int j = 0; j < 4; j++)
            #pragma unroll
            for (int p = 0; p < 4; p++) acc[i][j][p] = 0.0f;

    const int NT = K >> 5;

#define LOADT(kt, st) do {                                                    \
    _Pragma("unroll")                                                         \
    for (int rep = 0; rep < 2; rep++) {                                       \
        const int row = lrow + rep * 64;                                      \
        const size_t ga = (size_t)(bm + row) * lda + (size_t)(kt) * 32 + lg * 8; \
        const size_t gb = (size_t)(bn + row) * K + (size_t)(kt) * 32 + lg * 8; \
        const uint32_t so = smb + 2u * (uint32_t)((st) * STG_ELEMS + row * 40 + lg * 8); \
        CP16(so, A + ga);                                                     \
        CP16(so + 2 * 5120, W + gb);                                          \
    }                                                                         \
} while (0)

    LOADT(0, 0); CP_COMMIT();
    if (NT > 1) { LOADT(1, 1); CP_COMMIT(); }

    for (int kt = 0; kt < NT; kt++) {
        const int st = kt % 3;
        if (kt + 1 < NT) CP_WAIT1(); else CP_WAIT0();
        __syncthreads();
        if (kt + 2 < NT) { LOADT(kt + 2, (kt + 2) % 3); CP_COMMIT(); }

        const uint32_t As = smb + 2u * (uint32_t)(st * STG_ELEMS);
        const uint32_t Bs = As + 2u * 5120u;
        #pragma unroll
        for (int ks = 0; ks < 2; ks++) {
            uint32_t ah[4][4], bb[2][4];
            #pragma unroll
            for (int i = 0; i < 4; i++) {
                const uint32_t ad = As + 2u * (uint32_t)((wm * 64 + i * 16) * 40 + ks * 16) + 2u * offA;
                LDSM4(ah[i][0], ah[i][1], ah[i][2], ah[i][3], ad);
            }
            #pragma unroll
            for (int jj = 0; jj < 2; jj++) {
                const uint32_t bd = Bs + 2u * (uint32_t)((wn * 32 + jj * 16) * 40 + ks * 16) + 2u * offB;
                LDSM4(bb[jj][0], bb[jj][1], bb[jj][2], bb[jj][3], bd);
            }
            #pragma unroll
            for (int i = 0; i < 4; i++)
                #pragma unroll
                for (int j = 0; j < 4; j++)
                    mma16816(acc[i][j], ah[i], &bb[j >> 1][(j & 1) * 2]);
        }
        __syncthreads();
    }

    // epilogue
    int act = ACT;
    if (ACT == 5) {
        const int seg = bn >> 9;
        act = (seg == 1) ? 2 : (seg == 2) ? 1 : (seg == 4) ? 3 : 0;
    }
    #pragma unroll
    for (int i = 0; i < 4; i++) {
        const int r0 = bm + wm * 64 + i * 16 + group;
        #pragma unroll
        for (int j = 0; j < 4; j++) {
            const int c = bn + wn * 32 + j * 8 + qp * 2;
            const float2 bv = *(const float2*)(bias + c);
            float v0 = acc[i][j][0] + bv.x;
            float v1 = acc[i][j][1] + bv.y;
            float v2 = acc[i][j][2] + bv.x;
            float v3 = acc[i][j][3] + bv.y;
            if (ACT == 4) {
                const float2 ra = *(const float2*)(resid + (size_t)r0 * ldc + c);
                const float2 rb = *(const float2*)(resid + (size_t)(r0 + 8) * ldc + c);
                v0 += ra.x; v1 += ra.y; v2 += rb.x; v3 += rb.y;
            } else {
                v0 = act_apply(v0, act); v1 = act_apply(v1, act);
                v2 = act_apply(v2, act); v3 = act_apply(v3, act);
            }
            if (OUT == 0) {
                *(float2*)(C + (size_t)r0 * ldc + c)       = make_float2(v0, v1);
                *(float2*)(C + (size_t)(r0 + 8) * ldc + c) = make_float2(v2, v3);
            } else {
                *(__half2*)(Cf + (size_t)r0 * ldc + c)       = __floats2half2_rn(v0, v1);
                *(__half2*)(Cf + (size_t)(r0 + 8) * ldc + c) = __floats2half2_rn(v2, v3);
            }
        }
    }
#undef LOADT
}

// ---------------- scan passes ----------------
// proj row layout: [omega(0) | mag(512) | gate(1024) | qoff(1536) | p1(2048)]
__global__ void __launch_bounds__(Ddim)
passA_kernel(const float* __restrict__ x, const __half* __restrict__ proj,
             const __half* __restrict__ phii, const float* __restrict__ iscale,
             float4* __restrict__ csum)
{
    const int b = blockIdx.x / NC, c = blockIdx.x % NC, d = threadIdx.x;
    const float sc = fabsf(iscale[d]);
    size_t row = (size_t)b * Sdim + (size_t)c * CL;
    size_t idx = row * Ddim + d;
    size_t pidx = row * NPROJ + d;
    float rinc = 0.f, rmag = 0.f, rA = 0.f, rB = 0.f;
    #pragma unroll 2
    for (int s = 0; s < CL; s++, idx += Ddim, pidx += NPROJ) {
        float om = __half2float(proj[pidx]);
        float m  = __half2float(proj[pidx + 512]);
        float g  = __half2float(proj[pidx + 1024]);
        float xv = x[idx], pi = __half2float(phii[idx]);
        rinc += g * om * sc;
        float sp, cp;
        __sincosf(pi + rinc, &sp, &cp);
        float wc = m * xv;
        rA += wc * cp; rB += wc * sp; rmag += m;
    }
    csum[(size_t)blockIdx.x * Ddim + d] = make_float4(rinc, rmag, rA, rB);
}

__global__ void __launch_bounds__(Ddim)
passB_kernel(const float4* __restrict__ csum, float4* __restrict__ coff)
{
    const int b = blockIdx.x, d = threadIdx.x;
    float oi = 0.f, om = 0.f, omr = 0.f, omi = 0.f;
    #pragma unroll 4
    for (int c = 0; c < NC; c++) {
        const size_t i = ((size_t)b * NC + c) * Ddim + d;
        coff[i] = make_float4(oi, om, omr, omi);
        float4 s = csum[i];
        float st, ct;
        __sincosf(oi, &st, &ct);
        omr += ct * s.z - st * s.w;
        omi += st * s.z + ct * s.w;
        oi += s.x; om += s.y;
    }
}

__global__ void __launch_bounds__(Ddim)
passC_kernel(const float* __restrict__ x, const __half* __restrict__ proj,
             const __half* __restrict__ phii,
             const float* __restrict__ iscale, const float* __restrict__ lng,
             const float* __restrict__ lnb, const float4* __restrict__ coff,
             __half* __restrict__ ctx)
{
    __shared__ float2 warpred[16];
    __shared__ float2 bcast;
    const int b = blockIdx.x / NC, c = blockIdx.x % NC, d = threadIdx.x;
    const int lane = d & 31, wid = d >> 5;
    const float sc = fabsf(iscale[d]);
    const float g0 = lng[d], g1 = lng[Ddim + d], g2 = lng[2*Ddim+d], g3 = lng[3*Ddim+d];
    const float l0 = lnb[d], l1 = lnb[Ddim + d], l2 = lnb[2*Ddim+d], l3 = lnb[3*Ddim+d];

    float4 off = coff[(size_t)blockIdx.x * Ddim + d];
    float rinc = off.x, rmag = off.y, rmr = off.z, rmi = off.w;
    size_t row   = (size_t)b * Sdim + (size_t)c * CL;
    size_t idx   = row * Ddim + d;
    size_t pidx  = row * NPROJ + d;
    size_t cbase = row * (4 * Ddim) + d;

    for (int s = 0; s < CL; s++, idx += Ddim, pidx += NPROJ, cbase += 4 * Ddim) {
        float om = __half2float(proj[pidx]);
        float m  = __half2float(proj[pidx + 512]);
        float g  = __half2float(proj[pidx + 1024]);
        float qo = __half2float(proj[pidx + 1536]);
        float xv = x[idx], pi = __half2float(phii[idx]);
        rinc += g * om * sc;
        float phi = pi + rinc;
        float sp, cp;
        __sincosf(phi, &sp, &cp);
        float wc = m * xv;
        rmr += wc * cp; rmi += wc * sp; rmag += m;
        float rq = rsqrtf(rmag + 1e-8f);
        float mrv = rmr * rq, miv = rmi * rq;
        float sq, cq;
        __sincosf(phi + qo, &sq, &cq);
        float v0 = xv * cp, v1 = xv * sp;
        float v2 = mrv * cq + miv * sq;
        float v3 = miv * cq - mrv * sq;

        float lsum = v0 + v1 + v2 + v3;
        float lss  = v0 * v0 + v1 * v1 + v2 * v2 + v3 * v3;
        #pragma unroll
        for (int o = 16; o > 0; o >>= 1) {
            lsum += __shfl_down_sync(0xffffffffu, lsum, o);
            lss  += __shfl_down_sync(0xffffffffu, lss, o);
        }
        if (lane == 0) warpred[wid] = make_float2(lsum, lss);
        __syncthreads();
        if (wid == 0) {
            float2 t = (lane < 16) ? warpred[lane] : make_float2(0.f, 0.f);
            #pragma unroll
            for (int o = 8; o > 0; o >>= 1) {
                t.x += __shfl_down_sync(0xffffffffu, t.x, o);
                t.y += __shfl_down_sync(0xffffffffu, t.y, o);
            }
            if (lane == 0) bcast = t;
        }
        __syncthreads();
        const float mean = bcast.x * (1.0f / 2048.0f);
        const float var  = bcast.y * (1.0f / 2048.0f) - mean * mean;
        const float rstd = rsqrtf(var + 1e-5f);
        ctx[cbase           ] = __float2half((v0 - mean) * rstd * g0 + l0);
        ctx[cbase + Ddim    ] = __float2half((v1 - mean) * rstd * g1 + l1);
        ctx[cbase + 2 * Ddim] = __float2half((v2 - mean) * rstd * g2 + l2);
        ctx[cbase + 3 * Ddim] = __float2half((v3 - mean) * rstd * g3 + l3);
    }
}

// ---------------- launch ----------------
extern "C" void kernel_launch(void* const* d_in, const int* in_sizes, int n_in,
                              void* d_out, int out_size)
{
    const float* x       = (const float*)d_in[0];
    const float* W_omega = (const float*)d_in[1];
    const float* b_omega = (const float*)d_in[2];
    const float* W_p1    = (const float*)d_in[3];
    const float* b_p1    = (const float*)d_in[4];
    const float* W_p2    = (const float*)d_in[5];
    const float* b_p2    = (const float*)d_in[6];
    const float* W_gate  = (const float*)d_in[7];
    const float* b_gate  = (const float*)d_in[8];
    const float* iscale  = (const float*)d_in[9];
    const float* W_mag   = (const float*)d_in[10];
    const float* b_mag   = (const float*)d_in[11];
    const float* W_qoff  = (const float*)d_in[12];
    const float* b_qoff  = (const float*)d_in[13];
    const float* ln_g    = (const float*)d_in[14];
    const float* ln_b    = (const float*)d_in[15];
    const float* W_o1    = (const float*)d_in[16];
    const float* b_o1    = (const float*)d_in[17];
    const float* W_o2    = (const float*)d_in[18];
    const float* b_o2    = (const float*)d_in[19];
    float* out = (float*)d_out;

    __half *p_proj, *p_phii, *p_xf, *p_ctxf, *p_hf, *p_wf;
    float *p_bcat;
    float4 *p_csum, *p_coff;
    cudaGetSymbolAddress((void**)&p_proj,  g_proj);
    cudaGetSymbolAddress((void**)&p_phii,  g_phii);
    cudaGetSymbolAddress((void**)&p_xf,    g_xf);
    cudaGetSymbolAddress((void**)&p_ctxf,  g_ctxf);
    cudaGetSymbolAddress((void**)&p_hf,    g_hf);
    cudaGetSymbolAddress((void**)&p_wf,    g_wf);
    cudaGetSymbolAddress((void**)&p_bcat,  g_bcat);
    cudaGetSymbolAddress((void**)&p_csum,  g_csum);
    cudaGetSymbolAddress((void**)&p_coff,  g_coff);

    cudaFuncSetAttribute(mma_gemm<5,1>, cudaFuncAttributeMaxDynamicSharedMemorySize, SMEM_BYTES);
    cudaFuncSetAttribute(mma_gemm<0,1>, cudaFuncAttributeMaxDynamicSharedMemorySize, SMEM_BYTES);
    cudaFuncSetAttribute(mma_gemm<3,1>, cudaFuncAttributeMaxDynamicSharedMemorySize, SMEM_BYTES);
    cudaFuncSetAttribute(mma_gemm<4,0>, cudaFuncAttributeMaxDynamicSharedMemorySize, SMEM_BYTES);

    const dim3 tb(32, 8);
    // order matches proj segments: omega | mag | gate | qoff | p1 | p2
    wconv6_kernel<<<dim3(16, 16, 6), tb>>>(W_omega, W_mag, W_gate, W_qoff, W_p1, W_p2, p_wf);
    wconv_kernel<<<dim3(32, 64), tb>>>(W_o1, p_wf + OFF_O1, 2048, 1024);
    wconv_kernel<<<dim3(16, 32), tb>>>(W_o2, p_wf + OFF_O2, 1024, 512);

    fconv_kernel<<<(size_t)Mrows * Ddim / 4 / 256, 256>>>(x, p_xf);
    bcat_kernel<<<(NPROJ + 255) / 256, 256>>>(b_omega, b_mag, b_gate, b_qoff, b_p1, p_bcat);

    const dim3 blk(256);

    // Fused 5-projection GEMM: [M,512] @ [512,2560] -> proj (segmented act)
    mma_gemm<5,1><<<dim3(NPROJ / 128, Mrows / 128), blk, SMEM_BYTES>>>(
        p_xf, p_wf + OFF_OM, p_bcat, 0, 0, p_proj, 512, 512, NPROJ);

    // p2: phi_init = p1seg @ W_p2 + b_p2  (A strided out of proj buffer)
    mma_gemm<0,1><<<dim3(4, Mrows / 128), blk, SMEM_BYTES>>>(
        p_proj + 2048, p_wf + OFF_P2, b_p2, 0, 0, p_phii, 512, NPROJ, 512);

    passA_kernel<<<Bdim * NC, Ddim>>>(x, p_proj, p_phii, iscale, p_csum);
    passB_kernel<<<Bdim, Ddim>>>(p_csum, p_coff);
    passC_kernel<<<Bdim * NC, Ddim>>>(x, p_proj, p_phii, iscale, ln_g, ln_b,
                                      p_coff, p_ctxf);

    mma_gemm<3,1><<<dim3(8, Mrows / 128), blk, SMEM_BYTES>>>(
        p_ctxf, p_wf + OFF_O1, b_o1, 0, 0, p_hf, 2048, 2048, 1024);
    mma_gemm<4,0><<<dim3(4, Mrows / 128), blk, SMEM_BYTES>>>(
        p_hf, p_wf + OFF_O2, b_o2, x, out, 0, 1024, 1024, 512);
}

// round 9
// speedup vs baseline: 1.1584x; 1.0029x over previous
#include <cuda_runtime.h>
#include <cuda_fp16.h>
#include <math.h>
#include <stdint.h>

#define Bdim 8
#define Sdim 4096
#define Ddim 512
#define Mrows (Bdim * Sdim)
#define NC 64
#define CL (Sdim / NC)
#define NPROJ 2560   /* 5 fused projections */

// ---------------- scratch ----------------
__device__ __half g_proj[(size_t)Mrows * NPROJ];   // omega|mag|gate|qoff|p1
__device__ __half g_phii[(size_t)Mrows * Ddim];
__device__ __half g_xf  [(size_t)Mrows * Ddim];
__device__ __half g_ctxf[(size_t)Mrows * 4 * Ddim];
__device__ __half g_hf  [(size_t)Mrows * 2 * Ddim];
__device__ float4 g_csum[Bdim * NC * Ddim];
__device__ float4 g_coff[Bdim * NC * Ddim];
__device__ __half g_wf[4194304];
__device__ float  g_bcat[NPROJ];

#define OFF_OM   0
#define OFF_MAG  262144
#define OFF_GATE 524288
#define OFF_QOFF 786432
#define OFF_P1   1048576
#define OFF_P2   1310720
#define OFF_O1   1572864
#define OFF_O2   3670016

// ---------------- helpers ----------------
__device__ __forceinline__ uint32_t smem_u32(const void* p) {
    uint32_t a;
    asm("{ .reg .u64 t; cvta.to.shared.u64 t, %1; cvt.u32.u64 %0, t; }" : "=r"(a) : "l"(p));
    return a;
}
#define CP16(so, gp) \
    asm volatile("cp.async.cg.shared.global [%0], [%1], 16;" :: "r"(so), "l"(gp) : "memory")
#define CP_COMMIT() asm volatile("cp.async.commit_group;" ::: "memory")
#define CP_WAIT1()  asm volatile("cp.async.wait_group 1;" ::: "memory")
#define CP_WAIT0()  asm volatile("cp.async.wait_group 0;" ::: "memory")

#define LDSM4(r0, r1, r2, r3, a)                                              \
    asm volatile("ldmatrix.sync.aligned.m8n8.x4.shared.b16 {%0,%1,%2,%3}, [%4];" \
                 : "=r"(r0), "=r"(r1), "=r"(r2), "=r"(r3) : "r"(a))

__device__ __forceinline__ void mma16816(float* c, const uint32_t* a, const uint32_t* b) {
    asm volatile(
        "mma.sync.aligned.m16n8k16.row.col.f32.f16.f16.f32 "
        "{%0,%1,%2,%3}, {%4,%5,%6,%7}, {%8,%9}, {%0,%1,%2,%3};"
        : "+f"(c[0]), "+f"(c[1]), "+f"(c[2]), "+f"(c[3])
        : "r"(a[0]), "r"(a[1]), "r"(a[2]), "r"(a[3]), "r"(b[0]), "r"(b[1]));
}

__device__ __forceinline__ float act_apply(float v, int ACT) {
    if (ACT == 1) return 1.0f / (1.0f + __expf(-v));
    if (ACT == 2) return 5.0f / (1.0f + __expf(-v));
    if (ACT == 3) return 0.5f * v * (1.0f + erff(v * 0.70710678118654752f));
    return v;
}

// Batched: six 512x512 W[K,N] fp32 -> T[N,K] fp16 (transpose + convert)
__global__ void wconv6_kernel(const float* __restrict__ W0, const float* __restrict__ W1,
                              const float* __restrict__ W2, const float* __restrict__ W3,
                              const float* __restrict__ W4, const float* __restrict__ W5,
                              __half* __restrict__ T)
{
    __shared__ float t[32][33];
    const int z = blockIdx.z;
    const float* W = (z == 0) ? W0 : (z == 1) ? W1 : (z == 2) ? W2
                   : (z == 3) ? W3 : (z == 4) ? W4 : W5;
    __half* Tz = T + (size_t)z * 262144;
    const int tx = threadIdx.x, ty = threadIdx.y;
    const int n0 = blockIdx.x * 32, k0 = blockIdx.y * 32;
    #pragma unroll
    for (int i = 0; i < 32; i += 8)
        t[ty + i][tx] = W[(size_t)(k0 + ty + i) * 512 + n0 + tx];
    __syncthreads();
    #pragma unroll
    for (int i = 0; i < 32; i += 8)
        Tz[(size_t)(n0 + ty + i) * 512 + k0 + tx] = __float2half(t[tx][ty + i]);
}

__global__ void wconv_kernel(const float* __restrict__ W, __half* __restrict__ T,
                             int K, int N)
{
    __shared__ float t[32][33];
    const int tx = threadIdx.x, ty = threadIdx.y;
    const int n0 = blockIdx.x * 32, k0 = blockIdx.y * 32;
    #pragma unroll
    for (int i = 0; i < 32; i += 8)
        t[ty + i][tx] = W[(size_t)(k0 + ty + i) * N + n0 + tx];
    __syncthreads();
    #pragma unroll
    for (int i = 0; i < 32; i += 8)
        T[(size_t)(n0 + ty + i) * K + k0 + tx] = __float2half(t[tx][ty + i]);
}

// fp32 -> fp16 (x), with tail blocks doing the bias concat
__global__ void fconv_bcat_kernel(const float* __restrict__ X, __half* __restrict__ H,
                                  const float* b0, const float* b1, const float* b2,
                                  const float* b3, const float* b4, float* bout)
{
    const size_t nblk = (size_t)Mrows * Ddim / 4 / 256;
    if (blockIdx.x >= nblk) {
        const int i = (int)(blockIdx.x - nblk) * 256 + threadIdx.x;
        if (i < NPROJ) {
            const int seg = i >> 9, d = i & 511;
            const float* src = (seg == 0) ? b0 : (seg == 1) ? b1 : (seg == 2) ? b2
                                            : (seg == 3) ? b3 : b4;
            bout[i] = src[d];
        }
        return;
    }
    const size_t i = ((size_t)blockIdx.x * 256 + threadIdx.x) * 4;
    float4 v = *(const float4*)(X + i);
    *(__half2*)(H + i)     = __floats2half2_rn(v.x, v.y);
    *(__half2*)(H + i + 2) = __floats2half2_rn(v.z, v.w);
}

// ---------------------------------------------------------------------------
// fp16 HMMA GEMM: C = act(A[M,K](lda) @ W + bias) (+resid)
// CTA 128x128, BK=32, 256 thr, warp 64x32, 3-stage cp.async (proven cfg).
// ACT: 0 none, 1 sig, 2 5sig, 3 gelu, 4 resid-add, 5 segmented (bn>>9).
// OUT: 0 fp32, 1 fp16.
// ---------------------------------------------------------------------------
#define STG_ELEMS 10240
#define SMEM_BYTES (3 * STG_ELEMS * 2)

template <int ACT, int OUT>
__global__ void __launch_bounds__(256)
mma_gemm(const __half* __restrict__ A, const __half* __restrict__ W,
         const float* __restrict__ bias, const float* __restrict__ resid,
         float* __restrict__ C, __half* __restrict__ Cf,
         int K, int lda, int ldc)
{
    extern __shared__ __half sm[];
    const int tid = threadIdx.x;
    const int wid = tid >> 5, lane = tid & 31;
    const int wm = wid & 1, wn = wid >> 1;
    const int group = lane >> 2, qp = lane & 3;
    const int bn = blockIdx.x * 128, bm = blockIdx.y * 128;
    const uint32_t smb = smem_u32(sm);
    const int lrow = tid >> 2, lg = tid & 3;

    const uint32_t offA = (uint32_t)((lane & 7) * 40 + ((lane >> 3) & 1) * 320 + (lane >> 4) * 8);
    const uint32_t offB = (uint32_t)((lane & 7) * 40 + ((lane >> 3) & 1) * 8 + (lane >> 4) * 320);

    float acc[4][4][4];
    #pragma unroll
    for (int i = 0; i < 4; i++)
        #pragma unroll
        for (int j = 0; j < 4; j++)
            #pragma unroll
            for (int p = 0; p < 4; p++) acc[i][j][p] = 0.0f;

    const int NT = K >> 5;

#define LOADT(kt, st) do {                                                    \
    _Pragma("unroll")                                                         \
    for (int rep = 0; rep < 2; rep++) {                                       \
        const int row = lrow + rep * 64;                                      \
        const size_t ga = (size_t)(bm + row) * lda + (size_t)(kt) * 32 + lg * 8; \
        const size_t gb = (size_t)(bn + row) * K + (size_t)(kt) * 32 + lg * 8; \
        const uint32_t so = smb + 2u * (uint32_t)((st) * STG_ELEMS + row * 40 + lg * 8); \
        CP16(so, A + ga);                                                     \
        CP16(so + 2 * 5120, W + gb);                                          \
    }                                                                         \
} while (0)

    LOADT(0, 0); CP_COMMIT();
    if (NT > 1) { LOADT(1, 1); CP_COMMIT(); }

    for (int kt = 0; kt < NT; kt++) {
        const int st = kt % 3;
        if (kt + 1 < NT) CP_WAIT1(); else CP_WAIT0();
        __syncthreads();
        if (kt + 2 < NT) { LOADT(kt + 2, (kt + 2) % 3); CP_COMMIT(); }

        const uint32_t As = smb + 2u * (uint32_t)(st * STG_ELEMS);
        const uint32_t Bs = As + 2u * 5120u;
        #pragma unroll
        for (int ks = 0; ks < 2; ks++) {
            uint32_t ah[4][4], bb[2][4];
            #pragma unroll
            for (int i = 0; i < 4; i++) {
                const uint32_t ad = As + 2u * (uint32_t)((wm * 64 + i * 16) * 40 + ks * 16) + 2u * offA;
                LDSM4(ah[i][0], ah[i][1], ah[i][2], ah[i][3], ad);
            }
            #pragma unroll
            for (int jj = 0; jj < 2; jj++) {
                const uint32_t bd = Bs + 2u * (uint32_t)((wn * 32 + jj * 16) * 40 + ks * 16) + 2u * offB;
                LDSM4(bb[jj][0], bb[jj][1], bb[jj][2], bb[jj][3], bd);
            }
            #pragma unroll
            for (int i = 0; i < 4; i++)
                #pragma unroll
                for (int j = 0; j < 4; j++)
                    mma16816(acc[i][j], ah[i], &bb[j >> 1][(j & 1) * 2]);
        }
        __syncthreads();
    }

    // epilogue
    int act = ACT;
    if (ACT == 5) {
        const int seg = bn >> 9;
        act = (seg == 1) ? 2 : (seg == 2) ? 1 : (seg == 4) ? 3 : 0;
    }
    #pragma unroll
    for (int i = 0; i < 4; i++) {
        const int r0 = bm + wm * 64 + i * 16 + group;
        #pragma unroll
        for (int j = 0; j < 4; j++) {
            const int c = bn + wn * 32 + j * 8 + qp * 2;
            const float2 bv = *(const float2*)(bias + c);
            float v0 = acc[i][j][0] + bv.x;
            float v1 = acc[i][j][1] + bv.y;
            float v2 = acc[i][j][2] + bv.x;
            float v3 = acc[i][j][3] + bv.y;
            if (ACT == 4) {
                const float2 ra = *(const float2*)(resid + (size_t)r0 * ldc + c);
                const float2 rb = *(const float2*)(resid + (size_t)(r0 + 8) * ldc + c);
                v0 += ra.x; v1 += ra.y; v2 += rb.x; v3 += rb.y;
            } else {
                v0 = act_apply(v0, act); v1 = act_apply(v1, act);
                v2 = act_apply(v2, act); v3 = act_apply(v3, act);
            }
            if (OUT == 0) {
                *(float2*)(C + (size_t)r0 * ldc + c)       = make_float2(v0, v1);
                *(float2*)(C + (size_t)(r0 + 8) * ldc + c) = make_float2(v2, v3);
            } else {
                *(__half2*)(Cf + (size_t)r0 * ldc + c)       = __floats2half2_rn(v0, v1);
                *(__half2*)(Cf + (size_t)(r0 + 8) * ldc + c) = __floats2half2_rn(v2, v3);
            }
        }
    }
#undef LOADT
}

// ---------------- scan passes ----------------
// proj row layout: [omega(0) | mag(512) | gate(1024) | qoff(1536) | p1(2048)]
__global__ void __launch_bounds__(Ddim)
passA_kernel(const __half* __restrict__ xf, const __half* __restrict__ proj,
             const __half* __restrict__ phii, const float* __restrict__ iscale,
             float4* __restrict__ csum)
{
    const int b = blockIdx.x / NC, c = blockIdx.x % NC, d = threadIdx.x;
    const float sc = fabsf(iscale[d]);
    size_t row = (size_t)b * Sdim + (size_t)c * CL;
    size_t idx = row * Ddim + d;
    size_t pidx = row * NPROJ + d;
    float rinc = 0.f, rmag = 0.f, rA = 0.f, rB = 0.f;
    #pragma unroll 2
    for (int s = 0; s < CL; s++, idx += Ddim, pidx += NPROJ) {
        float om = __half2float(proj[pidx]);
        float m  = __half2float(proj[pidx + 512]);
        float g  = __half2float(proj[pidx + 1024]);
        float xv = __half2float(xf[idx]), pi = __half2float(phii[idx]);
        rinc += g * om * sc;
        float sp, cp;
        __sincosf(pi + rinc, &sp, &cp);
        float wc = m * xv;
        rA += wc * cp; rB += wc * sp; rmag += m;
    }
    csum[(size_t)blockIdx.x * Ddim + d] = make_float4(rinc, rmag, rA, rB);
}

__global__ void __launch_bounds__(Ddim)
passB_kernel(const float4* __restrict__ csum, float4* __restrict__ coff)
{
    const int b = blockIdx.x, d = threadIdx.x;
    float oi = 0.f, om = 0.f, omr = 0.f, omi = 0.f;
    #pragma unroll 4
    for (int c = 0; c < NC; c++) {
        const size_t i = ((size_t)b * NC + c) * Ddim + d;
        coff[i] = make_float4(oi, om, omr, omi);
        float4 s = csum[i];
        float st, ct;
        __sincosf(oi, &st, &ct);
        omr += ct * s.z - st * s.w;
        omi += st * s.z + ct * s.w;
        oi += s.x; om += s.y;
    }
}

__global__ void __launch_bounds__(Ddim)
passC_kernel(const __half* __restrict__ xf, const __half* __restrict__ proj,
             const __half* __restrict__ phii,
             const float* __restrict__ iscale, const float* __restrict__ lng,
             const float* __restrict__ lnb, const float4* __restrict__ coff,
             __half* __restrict__ ctx)
{
    __shared__ float2 warpred[2][16];
    const int b = blockIdx.x / NC, c = blockIdx.x % NC, d = threadIdx.x;
    const int lane = d & 31, wid = d >> 5;
    const float sc = fabsf(iscale[d]);
    const float g0 = lng[d], g1 = lng[Ddim + d], g2 = lng[2*Ddim+d], g3 = lng[3*Ddim+d];
    const float l0 = lnb[d], l1 = lnb[Ddim + d], l2 = lnb[2*Ddim+d], l3 = lnb[3*Ddim+d];

    float4 off = coff[(size_t)blockIdx.x * Ddim + d];
    float rinc = off.x, rmag = off.y, rmr = off.z, rmi = off.w;
    size_t row   = (size_t)b * Sdim + (size_t)c * CL;
    size_t idx   = row * Ddim + d;
    size_t pidx  = row * NPROJ + d;
    size_t cbase = row * (4 * Ddim) + d;

    for (int s = 0; s < CL; s++, idx += Ddim, pidx += NPROJ, cbase += 4 * Ddim) {
        float om = __half2float(proj[pidx]);
        float m  = __half2float(proj[pidx + 512]);
        float g  = __half2float(proj[pidx + 1024]);
        float qo = __half2float(proj[pidx + 1536]);
        float xv = __half2float(xf[idx]), pi = __half2float(phii[idx]);
        rinc += g * om * sc;
        float phi = pi + rinc;
        float sp, cp;
        __sincosf(phi, &sp, &cp);
        float wc = m * xv;
        rmr += wc * cp; rmi += wc * sp; rmag += m;
        float rq = rsqrtf(rmag + 1e-8f);
        float mrv = rmr * rq, miv = rmi * rq;
        float sq, cq;
        __sincosf(phi + qo, &sq, &cq);
        float v0 = xv * cp, v1 = xv * sp;
        float v2 = mrv * cq + miv * sq;
        float v3 = miv * cq - mrv * sq;

        // LN over 2048 vals: warp partials -> 1 barrier -> redundant butterfly
        float lsum = v0 + v1 + v2 + v3;
        float lss  = v0 * v0 + v1 * v1 + v2 * v2 + v3 * v3;
        #pragma unroll
        for (int o = 16; o > 0; o >>= 1) {
            lsum += __shfl_down_sync(0xffffffffu, lsum, o);
            lss  += __shfl_down_sync(0xffffffffu, lss, o);
        }
        const int pb = s & 1;
        if (lane == 0) warpred[pb][wid] = make_float2(lsum, lss);
        __syncthreads();
        float2 t = warpred[pb][lane & 15];
        #pragma unroll
        for (int o = 8; o > 0; o >>= 1) {
            t.x += __shfl_xor_sync(0xffffffffu, t.x, o);
            t.y += __shfl_xor_sync(0xffffffffu, t.y, o);
        }
        const float mean = t.x * (1.0f / 2048.0f);
        const float var  = t.y * (1.0f / 2048.0f) - mean * mean;
        const float rstd = rsqrtf(var + 1e-5f);
        ctx[cbase           ] = __float2half((v0 - mean) * rstd * g0 + l0);
        ctx[cbase + Ddim    ] = __float2half((v1 - mean) * rstd * g1 + l1);
        ctx[cbase + 2 * Ddim] = __float2half((v2 - mean) * rstd * g2 + l2);
        ctx[cbase + 3 * Ddim] = __float2half((v3 - mean) * rstd * g3 + l3);
    }
}

// ---------------- launch ----------------
extern "C" void kernel_launch(void* const* d_in, const int* in_sizes, int n_in,
                              void* d_out, int out_size)
{
    const float* x       = (const float*)d_in[0];
    const float* W_omega = (const float*)d_in[1];
    const float* b_omega = (const float*)d_in[2];
    const float* W_p1    = (const float*)d_in[3];
    const float* b_p1    = (const float*)d_in[4];
    const float* W_p2    = (const float*)d_in[5];
    const float* b_p2    = (const float*)d_in[6];
    const float* W_gate  = (const float*)d_in[7];
    const float* b_gate  = (const float*)d_in[8];
    const float* iscale  = (const float*)d_in[9];
    const float* W_mag   = (const float*)d_in[10];
    const float* b_mag   = (const float*)d_in[11];
    const float* W_qoff  = (const float*)d_in[12];
    const float* b_qoff  = (const float*)d_in[13];
    const float* ln_g    = (const float*)d_in[14];
    const float* ln_b    = (const float*)d_in[15];
    const float* W_o1    = (const float*)d_in[16];
    const float* b_o1    = (const float*)d_in[17];
    const float* W_o2    = (const float*)d_in[18];
    const float* b_o2    = (const float*)d_in[19];
    float* out = (float*)d_out;

    __half *p_proj, *p_phii, *p_xf, *p_ctxf, *p_hf, *p_wf;
    float *p_bcat;
    float4 *p_csum, *p_coff;
    cudaGetSymbolAddress((void**)&p_proj,  g_proj);
    cudaGetSymbolAddress((void**)&p_phii,  g_phii);
    cudaGetSymbolAddress((void**)&p_xf,    g_xf);
    cudaGetSymbolAddress((void**)&p_ctxf,  g_ctxf);
    cudaGetSymbolAddress((void**)&p_hf,    g_hf);
    cudaGetSymbolAddress((void**)&p_wf,    g_wf);
    cudaGetSymbolAddress((void**)&p_bcat,  g_bcat);
    cudaGetSymbolAddress((void**)&p_csum,  g_csum);
    cudaGetSymbolAddress((void**)&p_coff,  g_coff);

    cudaFuncSetAttribute(mma_gemm<5,1>, cudaFuncAttributeMaxDynamicSharedMemorySize, SMEM_BYTES);
    cudaFuncSetAttribute(mma_gemm<0,1>, cudaFuncAttributeMaxDynamicSharedMemorySize, SMEM_BYTES);
    cudaFuncSetAttribute(mma_gemm<3,1>, cudaFuncAttributeMaxDynamicSharedMemorySize, SMEM_BYTES);
    cudaFuncSetAttribute(mma_gemm<4,0>, cudaFuncAttributeMaxDynamicSharedMemorySize, SMEM_BYTES);

    const dim3 tb(32, 8);
    // order matches proj segments: omega | mag | gate | qoff | p1 | p2
    wconv6_kernel<<<dim3(16, 16, 6), tb>>>(W_omega, W_mag, W_gate, W_qoff, W_p1, W_p2, p_wf);
    wconv_kernel<<<dim3(32, 64), tb>>>(W_o1, p_wf + OFF_O1, 2048, 1024);
    wconv_kernel<<<dim3(16, 32), tb>>>(W_o2, p_wf + OFF_O2, 1024, 512);

    const unsigned fblocks = (unsigned)((size_t)Mrows * Ddim / 4 / 256);
    fconv_bcat_kernel<<<fblocks + (NPROJ + 255) / 256, 256>>>(
        x, p_xf, b_omega, b_mag, b_gate, b_qoff, b_p1, p_bcat);

    const dim3 blk(256);

    // Fused 5-projection GEMM: [M,512] @ [512,2560] -> proj (segmented act)
    mma_gemm<5,1><<<dim3(NPROJ / 128, Mrows / 128), blk, SMEM_BYTES>>>(
        p_xf, p_wf + OFF_OM, p_bcat, 0, 0, p_proj, 512, 512, NPROJ);

    // p2: phi_init = p1seg @ W_p2 + b_p2  (A strided out of proj buffer)
    mma_gemm<0,1><<<dim3(4, Mrows / 128), blk, SMEM_BYTES>>>(
        p_proj + 2048, p_wf + OFF_P2, b_p2, 0, 0, p_phii, 512, NPROJ, 512);

    passA_kernel<<<Bdim * NC, Ddim>>>(p_xf, p_proj, p_phii, iscale, p_csum);
    passB_kernel<<<Bdim, Ddim>>>(p_csum, p_coff);
    passC_kernel<<<Bdim * NC, Ddim>>>(p_xf, p_proj, p_phii, iscale, ln_g, ln_b,
                                      p_coff, p_ctxf);

    mma_gemm<3,1><<<dim3(8, Mrows / 128), blk, SMEM_BYTES>>>(
        p_ctxf, p_wf + OFF_O1, b_o1, 0, 0, p_hf, 2048, 2048, 1024);
    mma_gemm<4,0><<<dim3(4, Mrows / 128), blk, SMEM_BYTES>>>(
        p_hf, p_wf + OFF_O2, b_o2, x, out, 0, 1024, 1024, 512);
}

// round 10
// speedup vs baseline: 1.2288x; 1.0607x over previous
#include <cuda_runtime.h>
#include <cuda_fp16.h>
#include <math.h>
#include <stdint.h>

#define Bdim 8
#define Sdim 4096
#define Ddim 512
#define Mrows (Bdim * Sdim)
#define NC 128
#define CL (Sdim / NC)
#define NPROJ 2560   /* 5 fused projections */

// ---------------- scratch ----------------
__device__ __half g_proj[(size_t)Mrows * NPROJ];   // omega|mag|gate|qoff|p1
__device__ __half g_phii[(size_t)Mrows * Ddim];
__device__ __half g_xf  [(size_t)Mrows * Ddim];
__device__ __half g_ctxf[(size_t)Mrows * 4 * Ddim];
__device__ __half g_hf  [(size_t)Mrows * 2 * Ddim];
__device__ float4 g_csum[Bdim * NC * Ddim];
__device__ float4 g_coff[Bdim * NC * Ddim];
__device__ __half g_wf[4194304];
__device__ float  g_bcat[NPROJ];

#define OFF_OM   0
#define OFF_MAG  262144
#define OFF_GATE 524288
#define OFF_QOFF 786432
#define OFF_P1   1048576
#define OFF_P2   1310720
#define OFF_O1   1572864
#define OFF_O2   3670016

// ---------------- helpers ----------------
__device__ __forceinline__ uint32_t smem_u32(const void* p) {
    uint32_t a;
    asm("{ .reg .u64 t; cvta.to.shared.u64 t, %1; cvt.u32.u64 %0, t; }" : "=r"(a) : "l"(p));
    return a;
}
#define CP16(so, gp) \
    asm volatile("cp.async.cg.shared.global [%0], [%1], 16;" :: "r"(so), "l"(gp) : "memory")
#define CP_COMMIT() asm volatile("cp.async.commit_group;" ::: "memory")
#define CP_WAIT1()  asm volatile("cp.async.wait_group 1;" ::: "memory")
#define CP_WAIT0()  asm volatile("cp.async.wait_group 0;" ::: "memory")

#define LDSM4(r0, r1, r2, r3, a)                                              \
    asm volatile("ldmatrix.sync.aligned.m8n8.x4.shared.b16 {%0,%1,%2,%3}, [%4];" \
                 : "=r"(r0), "=r"(r1), "=r"(r2), "=r"(r3) : "r"(a))

__device__ __forceinline__ void mma16816(float* c, const uint32_t* a, const uint32_t* b) {
    asm volatile(
        "mma.sync.aligned.m16n8k16.row.col.f32.f16.f16.f32 "
        "{%0,%1,%2,%3}, {%4,%5,%6,%7}, {%8,%9}, {%0,%1,%2,%3};"
        : "+f"(c[0]), "+f"(c[1]), "+f"(c[2]), "+f"(c[3])
        : "r"(a[0]), "r"(a[1]), "r"(a[2]), "r"(a[3]), "r"(b[0]), "r"(b[1]));
}

__device__ __forceinline__ float act_apply(float v, int ACT) {
    if (ACT == 1) return 1.0f / (1.0f + __expf(-v));
    if (ACT == 2) return 5.0f / (1.0f + __expf(-v));
    if (ACT == 3) return 0.5f * v * (1.0f + erff(v * 0.70710678118654752f));
    return v;
}

// Batched: six 512x512 W[K,N] fp32 -> T[N,K] fp16 (transpose + convert)
__global__ void wconv6_kernel(const float* __restrict__ W0, const float* __restrict__ W1,
                              const float* __restrict__ W2, const float* __restrict__ W3,
                              const float* __restrict__ W4, const float* __restrict__ W5,
                              __half* __restrict__ T)
{
    __shared__ float t[32][33];
    const int z = blockIdx.z;
    const float* W = (z == 0) ? W0 : (z == 1) ? W1 : (z == 2) ? W2
                   : (z == 3) ? W3 : (z == 4) ? W4 : W5;
    __half* Tz = T + (size_t)z * 262144;
    const int tx = threadIdx.x, ty = threadIdx.y;
    const int n0 = blockIdx.x * 32, k0 = blockIdx.y * 32;
    #pragma unroll
    for (int i = 0; i < 32; i += 8)
        t[ty + i][tx] = W[(size_t)(k0 + ty + i) * 512 + n0 + tx];
    __syncthreads();
    #pragma unroll
    for (int i = 0; i < 32; i += 8)
        Tz[(size_t)(n0 + ty + i) * 512 + k0 + tx] = __float2half(t[tx][ty + i]);
}

__global__ void wconv_kernel(const float* __restrict__ W, __half* __restrict__ T,
                             int K, int N)
{
    __shared__ float t[32][33];
    const int tx = threadIdx.x, ty = threadIdx.y;
    const int n0 = blockIdx.x * 32, k0 = blockIdx.y * 32;
    #pragma unroll
    for (int i = 0; i < 32; i += 8)
        t[ty + i][tx] = W[(size_t)(k0 + ty + i) * N + n0 + tx];
    __syncthreads();
    #pragma unroll
    for (int i = 0; i < 32; i += 8)
        T[(size_t)(n0 + ty + i) * K + k0 + tx] = __float2half(t[tx][ty + i]);
}

// fp32 -> fp16 (x), with tail blocks doing the bias concat
__global__ void fconv_bcat_kernel(const float* __restrict__ X, __half* __restrict__ H,
                                  const float* b0, const float* b1, const float* b2,
                                  const float* b3, const float* b4, float* bout)
{
    const size_t nblk = (size_t)Mrows * Ddim / 4 / 256;
    if (blockIdx.x >= nblk) {
        const int i = (int)(blockIdx.x - nblk) * 256 + threadIdx.x;
        if (i < NPROJ) {
            const int seg = i >> 9, d = i & 511;
            const float* src = (seg == 0) ? b0 : (seg == 1) ? b1 : (seg == 2) ? b2
                                            : (seg == 3) ? b3 : b4;
            bout[i] = src[d];
        }
        return;
    }
    const size_t i = ((size_t)blockIdx.x * 256 + threadIdx.x) * 4;
    float4 v = *(const float4*)(X + i);
    *(__half2*)(H + i)     = __floats2half2_rn(v.x, v.y);
    *(__half2*)(H + i + 2) = __floats2half2_rn(v.z, v.w);
}

// ---------------------------------------------------------------------------
// fp16 HMMA GEMM: C = act(A[M,K](lda) @ W + bias) (+resid)
// CTA 128x128, BK=32, 256 thr, warp 64x32, 3-stage cp.async (proven cfg).
// ACT: 0 none, 1 sig, 2 5sig, 3 gelu, 4 resid-add, 5 segmented (bn>>9).
// OUT: 0 fp32, 1 fp16.
// ---------------------------------------------------------------------------
#define STG_ELEMS 10240
#define SMEM_BYTES (3 * STG_ELEMS * 2)

template <int ACT, int OUT>
__global__ void __launch_bounds__(256)
mma_gemm(const __half* __restrict__ A, const __half* __restrict__ W,
         const float* __restrict__ bias, const float* __restrict__ resid,
         float* __restrict__ C, __half* __restrict__ Cf,
         int K, int lda, int ldc)
{
    extern __shared__ __half sm[];
    const int tid = threadIdx.x;
    const int wid = tid >> 5, lane = tid & 31;
    const int wm = wid & 1, wn = wid >> 1;
    const int group = lane >> 2, qp = lane & 3;
    const int bn = blockIdx.x * 128, bm = blockIdx.y * 128;
    const uint32_t smb = smem_u32(sm);
    const int lrow = tid >> 2, lg = tid & 3;

    const uint32_t offA = (uint32_t)((lane & 7) * 40 + ((lane >> 3) & 1) * 320 + (lane >> 4) * 8);
    const uint32_t offB = (uint32_t)((lane & 7) * 40 + ((lane >> 3) & 1) * 8 + (lane >> 4) * 320);

    float acc[4][4][4];
    #pragma unroll
    for (int i = 0; i < 4; i++)
        #pragma unroll
        for (int j = 0; j < 4; j++)
            #pragma unroll
            for (int p = 0; p < 4; p++) acc[i][j][p] = 0.0f;

    const int NT = K >> 5;

#define LOADT(kt, st) do {                                                    \
    _Pragma("unroll")                                                         \
    for (int rep = 0; rep < 2; rep++) {                                       \
        const int row = lrow + rep * 64;                                      \
        const size_t ga = (size_t)(bm + row) * lda + (size_t)(kt) * 32 + lg * 8; \
        const size_t gb = (size_t)(bn + row) * K + (size_t)(kt) * 32 + lg * 8; \
        const uint32_t so = smb + 2u * (uint32_t)((st) * STG_ELEMS + row * 40 + lg * 8); \
        CP16(so, A + ga);                                                     \
        CP16(so + 2 * 5120, W + gb);                                          \
    }                                                                         \
} while (0)

    LOADT(0, 0); CP_COMMIT();
    if (NT > 1) { LOADT(1, 1); CP_COMMIT(); }

    for (int kt = 0; kt < NT; kt++) {
        const int st = kt % 3;
        if (kt + 1 < NT) CP_WAIT1(); else CP_WAIT0();
        __syncthreads();
        if (kt + 2 < NT) { LOADT(kt + 2, (kt + 2) % 3); CP_COMMIT(); }

        const uint32_t As = smb + 2u * (uint32_t)(st * STG_ELEMS);
        const uint32_t Bs = As + 2u * 5120u;
        #pragma unroll
        for (int ks = 0; ks < 2; ks++) {
            uint32_t ah[4][4], bb[2][4];
            #pragma unroll
            for (int i = 0; i < 4; i++) {
                const uint32_t ad = As + 2u * (uint32_t)((wm * 64 + i * 16) * 40 + ks * 16) + 2u * offA;
                LDSM4(ah[i][0], ah[i][1], ah[i][2], ah[i][3], ad);
            }
            #pragma unroll
            for (int jj = 0; jj < 2; jj++) {
                const uint32_t bd = Bs + 2u * (uint32_t)((wn * 32 + jj * 16) * 40 + ks * 16) + 2u * offB;
                LDSM4(bb[jj][0], bb[jj][1], bb[jj][2], bb[jj][3], bd);
            }
            #pragma unroll
            for (int i = 0; i < 4; i++)
                #pragma unroll
                for (int j = 0; j < 4; j++)
                    mma16816(acc[i][j], ah[i], &bb[j >> 1][(j & 1) * 2]);
        }
        __syncthreads();
    }

    // epilogue
    int act = ACT;
    if (ACT == 5) {
        const int seg = bn >> 9;
        act = (seg == 1) ? 2 : (seg == 2) ? 1 : (seg == 4) ? 3 : 0;
    }
    #pragma unroll
    for (int i = 0; i < 4; i++) {
        const int r0 = bm + wm * 64 + i * 16 + group;
        #pragma unroll
        for (int j = 0; j < 4; j++) {
            const int c = bn + wn * 32 + j * 8 + qp * 2;
            const float2 bv = *(const float2*)(bias + c);
            float v0 = acc[i][j][0] + bv.x;
            float v1 = acc[i][j][1] + bv.y;
            float v2 = acc[i][j][2] + bv.x;
            float v3 = acc[i][j][3] + bv.y;
            if (ACT == 4) {
                const float2 ra = *(const float2*)(resid + (size_t)r0 * ldc + c);
                const float2 rb = *(const float2*)(resid + (size_t)(r0 + 8) * ldc + c);
                v0 += ra.x; v1 += ra.y; v2 += rb.x; v3 += rb.y;
            } else {
                v0 = act_apply(v0, act); v1 = act_apply(v1, act);
                v2 = act_apply(v2, act); v3 = act_apply(v3, act);
            }
            if (OUT == 0) {
                *(float2*)(C + (size_t)r0 * ldc + c)       = make_float2(v0, v1);
                *(float2*)(C + (size_t)(r0 + 8) * ldc + c) = make_float2(v2, v3);
            } else {
                *(__half2*)(Cf + (size_t)r0 * ldc + c)       = __floats2half2_rn(v0, v1);
                *(__half2*)(Cf + (size_t)(r0 + 8) * ldc + c) = __floats2half2_rn(v2, v3);
            }
        }
    }
#undef LOADT
}

// ---------------- scan passes (half2-vectorized, 2 d-channels/thread) ----------------
// proj row layout: [omega(0) | mag(512) | gate(1024) | qoff(1536) | p1(2048)]
__global__ void __launch_bounds__(256)
passA_kernel(const __half* __restrict__ xf, const __half* __restrict__ proj,
             const __half* __restrict__ phii, const float* __restrict__ iscale,
             float4* __restrict__ csum)
{
    const int b = blockIdx.x / NC, c = blockIdx.x % NC;
    const int d0 = threadIdx.x * 2;
    const float2 sc2 = *(const float2*)(iscale + d0);
    const float sca = fabsf(sc2.x), scb = fabsf(sc2.y);
    size_t row = (size_t)b * Sdim + (size_t)c * CL;
    size_t idx = row * Ddim + d0;
    size_t pidx = row * NPROJ + d0;
    float ria = 0.f, rma = 0.f, rAa = 0.f, rBa = 0.f;
    float rib = 0.f, rmb = 0.f, rAb = 0.f, rBb = 0.f;
    #pragma unroll 2
    for (int s = 0; s < CL; s++, idx += Ddim, pidx += NPROJ) {
        const float2 om = __half22float2(*(const __half2*)(proj + pidx));
        const float2 m  = __half22float2(*(const __half2*)(proj + pidx + 512));
        const float2 g  = __half22float2(*(const __half2*)(proj + pidx + 1024));
        const float2 xv = __half22float2(*(const __half2*)(xf + idx));
        const float2 pi = __half22float2(*(const __half2*)(phii + idx));
        ria += g.x * om.x * sca;
        rib += g.y * om.y * scb;
        float spa, cpa, spb, cpb;
        __sincosf(pi.x + ria, &spa, &cpa);
        __sincosf(pi.y + rib, &spb, &cpb);
        const float wca = m.x * xv.x, wcb = m.y * xv.y;
        rAa += wca * cpa; rBa += wca * spa; rma += m.x;
        rAb += wcb * cpb; rBb += wcb * spb; rmb += m.y;
    }
    csum[(size_t)blockIdx.x * Ddim + d0]     = make_float4(ria, rma, rAa, rBa);
    csum[(size_t)blockIdx.x * Ddim + d0 + 1] = make_float4(rib, rmb, rAb, rBb);
}

__global__ void __launch_bounds__(Ddim)
passB_kernel(const float4* __restrict__ csum, float4* __restrict__ coff)
{
    const int b = blockIdx.x, d = threadIdx.x;
    float oi = 0.f, om = 0.f, omr = 0.f, omi = 0.f;
    #pragma unroll 4
    for (int c = 0; c < NC; c++) {
        const size_t i = ((size_t)b * NC + c) * Ddim + d;
        coff[i] = make_float4(oi, om, omr, omi);
        float4 s = csum[i];
        float st, ct;
        __sincosf(oi, &st, &ct);
        omr += ct * s.z - st * s.w;
        omi += st * s.z + ct * s.w;
        oi += s.x; om += s.y;
    }
}

__global__ void __launch_bounds__(256)
passC_kernel(const __half* __restrict__ xf, const __half* __restrict__ proj,
             const __half* __restrict__ phii,
             const float* __restrict__ iscale, const float* __restrict__ lng,
             const float* __restrict__ lnb, const float4* __restrict__ coff,
             __half* __restrict__ ctx)
{
    __shared__ float2 warpred[2][8];
    const int b = blockIdx.x / NC, c = blockIdx.x % NC;
    const int d0 = threadIdx.x * 2;
    const int lane = threadIdx.x & 31, wid = threadIdx.x >> 5;
    const float2 sc2 = *(const float2*)(iscale + d0);
    const float sca = fabsf(sc2.x), scb = fabsf(sc2.y);
    float2 lg0 = *(const float2*)(lng + d0);
    float2 lg1 = *(const float2*)(lng + Ddim + d0);
    float2 lg2 = *(const float2*)(lng + 2 * Ddim + d0);
    float2 lg3 = *(const float2*)(lng + 3 * Ddim + d0);
    float2 lb0 = *(const float2*)(lnb + d0);
    float2 lb1 = *(const float2*)(lnb + Ddim + d0);
    float2 lb2 = *(const float2*)(lnb + 2 * Ddim + d0);
    float2 lb3 = *(const float2*)(lnb + 3 * Ddim + d0);

    float4 ofa = coff[(size_t)blockIdx.x * Ddim + d0];
    float4 ofb = coff[(size_t)blockIdx.x * Ddim + d0 + 1];
    float ria = ofa.x, rma = ofa.y, rra = ofa.z, rib_ = ofa.w;
    float rib = ofb.x, rmb = ofb.y, rrb = ofb.z, rib2 = ofb.w;
    // rename: (ria,rma,rra,rib_) = (rinc, rmag, mem_r, mem_i) channel a
    //         (rib,rmb,rrb,rib2) likewise channel b
    size_t row   = (size_t)b * Sdim + (size_t)c * CL;
    size_t idx   = row * Ddim + d0;
    size_t pidx  = row * NPROJ + d0;
    size_t cbase = row * (4 * Ddim) + d0;

    for (int s = 0; s < CL; s++, idx += Ddim, pidx += NPROJ, cbase += 4 * Ddim) {
        const float2 om = __half22float2(*(const __half2*)(proj + pidx));
        const float2 m  = __half22float2(*(const __half2*)(proj + pidx + 512));
        const float2 g  = __half22float2(*(const __half2*)(proj + pidx + 1024));
        const float2 qo = __half22float2(*(const __half2*)(proj + pidx + 1536));
        const float2 xv = __half22float2(*(const __half2*)(xf + idx));
        const float2 pi = __half22float2(*(const __half2*)(phii + idx));

        ria += g.x * om.x * sca;
        rib += g.y * om.y * scb;
        const float phia = pi.x + ria, phib = pi.y + rib;
        float spa, cpa, spb, cpb;
        __sincosf(phia, &spa, &cpa);
        __sincosf(phib, &spb, &cpb);
        const float wca = m.x * xv.x, wcb = m.y * xv.y;
        rra  += wca * cpa; rib_ += wca * spa; rma += m.x;
        rrb  += wcb * cpb; rib2 += wcb * spb; rmb += m.y;
        const float rqa = rsqrtf(rma + 1e-8f), rqb = rsqrtf(rmb + 1e-8f);
        const float mra = rra * rqa, mia = rib_ * rqa;
        const float mrb = rrb * rqb, mib = rib2 * rqb;
        float sqa, cqa, sqb, cqb;
        __sincosf(phia + qo.x, &sqa, &cqa);
        __sincosf(phib + qo.y, &sqb, &cqb);
        const float v0a = xv.x * cpa, v1a = xv.x * spa;
        const float v2a = mra * cqa + mia * sqa;
        const float v3a = mia * cqa - mra * sqa;
        const float v0b = xv.y * cpb, v1b = xv.y * spb;
        const float v2b = mrb * cqb + mib * sqb;
        const float v3b = mib * cqb - mrb * sqb;

        float lsum = v0a + v1a + v2a + v3a + v0b + v1b + v2b + v3b;
        float lss  = v0a * v0a + v1a * v1a + v2a * v2a + v3a * v3a
                   + v0b * v0b + v1b * v1b + v2b * v2b + v3b * v3b;
        #pragma unroll
        for (int o = 16; o > 0; o >>= 1) {
            lsum += __shfl_down_sync(0xffffffffu, lsum, o);
            lss  += __shfl_down_sync(0xffffffffu, lss, o);
        }
        const int pb = s & 1;
        if (lane == 0) warpred[pb][wid] = make_float2(lsum, lss);
        __syncthreads();
        float2 t = warpred[pb][lane & 7];
        #pragma unroll
        for (int o = 4; o > 0; o >>= 1) {
            t.x += __shfl_xor_sync(0xffffffffu, t.x, o);
            t.y += __shfl_xor_sync(0xffffffffu, t.y, o);
        }
        const float mean = t.x * (1.0f / 2048.0f);
        const float var  = t.y * (1.0f / 2048.0f) - mean * mean;
        const float rstd = rsqrtf(var + 1e-5f);

        *(__half2*)(ctx + cbase) = __floats2half2_rn(
            (v0a - mean) * rstd * lg0.x + lb0.x, (v0b - mean) * rstd * lg0.y + lb0.y);
        *(__half2*)(ctx + cbase + Ddim) = __floats2half2_rn(
            (v1a - mean) * rstd * lg1.x + lb1.x, (v1b - mean) * rstd * lg1.y + lb1.y);
        *(__half2*)(ctx + cbase + 2 * Ddim) = __floats2half2_rn(
            (v2a - mean) * rstd * lg2.x + lb2.x, (v2b - mean) * rstd * lg2.y + lb2.y);
        *(__half2*)(ctx + cbase + 3 * Ddim) = __floats2half2_rn(
            (v3a - mean) * rstd * lg3.x + lb3.x, (v3b - mean) * rstd * lg3.y + lb3.y);
    }
}

// ---------------- launch ----------------
extern "C" void kernel_launch(void* const* d_in, const int* in_sizes, int n_in,
                              void* d_out, int out_size)
{
    const float* x       = (const float*)d_in[0];
    const float* W_omega = (const float*)d_in[1];
    const float* b_omega = (const float*)d_in[2];
    const float* W_p1    = (const float*)d_in[3];
    const float* b_p1    = (const float*)d_in[4];
    const float* W_p2    = (const float*)d_in[5];
    const float* b_p2    = (const float*)d_in[6];
    const float* W_gate  = (const float*)d_in[7];
    const float* b_gate  = (const float*)d_in[8];
    const float* iscale  = (const float*)d_in[9];
    const float* W_mag   = (const float*)d_in[10];
    const float* b_mag   = (const float*)d_in[11];
    const float* W_qoff  = (const float*)d_in[12];
    const float* b_qoff  = (const float*)d_in[13];
    const float* ln_g    = (const float*)d_in[14];
    const float* ln_b    = (const float*)d_in[15];
    const float* W_o1    = (const float*)d_in[16];
    const float* b_o1    = (const float*)d_in[17];
    const float* W_o2    = (const float*)d_in[18];
    const float* b_o2    = (const float*)d_in[19];
    float* out = (float*)d_out;

    __half *p_proj, *p_phii, *p_xf, *p_ctxf, *p_hf, *p_wf;
    float *p_bcat;
    float4 *p_csum, *p_coff;
    cudaGetSymbolAddress((void**)&p_proj,  g_proj);
    cudaGetSymbolAddress((void**)&p_phii,  g_phii);
    cudaGetSymbolAddress((void**)&p_xf,    g_xf);
    cudaGetSymbolAddress((void**)&p_ctxf,  g_ctxf);
    cudaGetSymbolAddress((void**)&p_hf,    g_hf);
    cudaGetSymbolAddress((void**)&p_wf,    g_wf);
    cudaGetSymbolAddress((void**)&p_bcat,  g_bcat);
    cudaGetSymbolAddress((void**)&p_csum,  g_csum);
    cudaGetSymbolAddress((void**)&p_coff,  g_coff);

    cudaFuncSetAttribute(mma_gemm<5,1>, cudaFuncAttributeMaxDynamicSharedMemorySize, SMEM_BYTES);
    cudaFuncSetAttribute(mma_gemm<0,1>, cudaFuncAttributeMaxDynamicSharedMemorySize, SMEM_BYTES);
    cudaFuncSetAttribute(mma_gemm<3,1>, cudaFuncAttributeMaxDynamicSharedMemorySize, SMEM_BYTES);
    cudaFuncSetAttribute(mma_gemm<4,0>, cudaFuncAttributeMaxDynamicSharedMemorySize, SMEM_BYTES);

    const dim3 tb(32, 8);
    // order matches proj segments: omega | mag | gate | qoff | p1 | p2
    wconv6_kernel<<<dim3(16, 16, 6), tb>>>(W_omega, W_mag, W_gate, W_qoff, W_p1, W_p2, p_wf);
    wconv_kernel<<<dim3(32, 64), tb>>>(W_o1, p_wf + OFF_O1, 2048, 1024);
    wconv_kernel<<<dim3(16, 32), tb>>>(W_o2, p_wf + OFF_O2, 1024, 512);

    const unsigned fblocks = (unsigned)((size_t)Mrows * Ddim / 4 / 256);
    fconv_bcat_kernel<<<fblocks + (NPROJ + 255) / 256, 256>>>(
        x, p_xf, b_omega, b_mag, b_gate, b_qoff, b_p1, p_bcat);

    const dim3 blk(256);

    // Fused 5-projection GEMM: [M,512] @ [512,2560] -> proj (segmented act)
    mma_gemm<5,1><<<dim3(NPROJ / 128, Mrows / 128), blk, SMEM_BYTES>>>(
        p_xf, p_wf + OFF_OM, p_bcat, 0, 0, p_proj, 512, 512, NPROJ);

    // p2: phi_init = p1seg @ W_p2 + b_p2  (A strided out of proj buffer)
    mma_gemm<0,1><<<dim3(4, Mrows / 128), blk, SMEM_BYTES>>>(
        p_proj + 2048, p_wf + OFF_P2, b_p2, 0, 0, p_phii, 512, NPROJ, 512);

    passA_kernel<<<Bdim * NC, 256>>>(p_xf, p_proj, p_phii, iscale, p_csum);
    passB_kernel<<<Bdim, Ddim>>>(p_csum, p_coff);
    passC_kernel<<<Bdim * NC, 256>>>(p_xf, p_proj, p_phii, iscale, ln_g, ln_b,
                                     p_coff, p_ctxf);

    mma_gemm<3,1><<<dim3(8, Mrows / 128), blk, SMEM_BYTES>>>(
        p_ctxf, p_wf + OFF_O1, b_o1, 0, 0, p_hf, 2048, 2048, 1024);
    mma_gemm<4,0><<<dim3(4, Mrows / 128), blk, SMEM_BYTES>>>(
        p_hf, p_wf + OFF_O2, b_o2, x, out, 0, 1024, 1024, 512);
}